// round 14
// baseline (speedup 1.0000x reference)
#include <cuda_runtime.h>
#include <math.h>
#include <stdint.h>

#define NPIX 4096
#define CDIM 256
#define NLOW 256
#define KLEN 32
#define BATCH 2
#define CW 128              // words (half2) per channel row

// ---------------- scratch (no allocations allowed) ----------------
__device__ float    g_q[BATCH * NPIX * CDIM];
__device__ float    g_k[BATCH * NPIX * CDIM];
__device__ float    g_v[BATCH * NPIX * CDIM];
__device__ float    g_x[BATCH * NPIX * CDIM];
__device__ uint32_t g_w[4 * CDIM * CDIM / 2];   // W^T as half2: [which][cout][k/2]
__device__ int      g_idx[BATCH * NLOW * KLEN];

// ---------------- helpers ----------------
__device__ __forceinline__ uint32_t pk2(float lo, float hi) {
    uint32_t r;
    asm("cvt.rn.f16x2.f32 %0, %1, %2;" : "=r"(r) : "f"(hi), "f"(lo));
    return r;
}
__device__ __forceinline__ uint32_t prmt(uint32_t a, uint32_t b, uint32_t sel) {
    uint32_t r;
    asm("prmt.b32 %0, %1, %2, %3;" : "=r"(r) : "r"(a), "r"(b), "r"(sel));
    return r;
}
__device__ __forceinline__ void mma_f16(float* c, const uint32_t* a, const uint32_t* b) {
    asm volatile(
        "mma.sync.aligned.m16n8k16.row.col.f32.f16.f16.f32 "
        "{%0,%1,%2,%3},{%4,%5,%6,%7},{%8,%9},{%0,%1,%2,%3};"
        : "+f"(c[0]), "+f"(c[1]), "+f"(c[2]), "+f"(c[3])
        : "r"(a[0]), "r"(a[1]), "r"(a[2]), "r"(a[3]), "r"(b[0]), "r"(b[1]));
}
__device__ __forceinline__ void cp16(const void* dst, const void* src) {
    uint32_t d = (uint32_t)__cvta_generic_to_shared(dst);
    asm volatile("cp.async.cg.shared.global [%0], [%1], 16;" :: "r"(d), "l"(src));
}
#define CP_COMMIT() asm volatile("cp.async.commit_group;" ::: "memory")
#define CP_WAIT0()  asm volatile("cp.async.wait_group 0;" ::: "memory")
#define CP_WAIT1()  asm volatile("cp.async.wait_group 1;" ::: "memory")

// ---------------- prep: topk (blocks 0..63) + weight transpose->half2 (64..191) ----------------
__global__ __launch_bounds__(256) void prep_kernel(const float* __restrict__ cmap,
                                                   int* __restrict__ idx,
                                                   const float* __restrict__ Wq,
                                                   const float* __restrict__ Wk,
                                                   const float* __restrict__ Wv,
                                                   const float* __restrict__ Wo,
                                                   uint32_t* __restrict__ wt) {
    __shared__ float sm[64][33];
    int t = threadIdx.x;
    if (blockIdx.x < 64) {
        int lane = t & 31;
        int row  = blockIdx.x * 8 + (t >> 5);
        const float* r = cmap + (size_t)row * NLOW;
        float m1 = -1e30f, m2 = -1e30f;
        int i1 = 0, i2 = 0;
        #pragma unroll
        for (int l = 0; l < 8; l++) {
            int j = l * 32 + lane;
            float v = r[j];
            if (v > m1)      { m2 = m1; i2 = i1; m1 = v; i1 = j; }
            else if (v > m2) { m2 = v;  i2 = j; }
        }
        #pragma unroll
        for (int off = 16; off > 0; off >>= 1) {
            float om1 = __shfl_xor_sync(0xffffffffu, m1, off);
            float om2 = __shfl_xor_sync(0xffffffffu, m2, off);
            int   oi1 = __shfl_xor_sync(0xffffffffu, i1, off);
            int   oi2 = __shfl_xor_sync(0xffffffffu, i2, off);
            if (om1 > m1) {
                if (m1 > om2) { m2 = m1; i2 = i1; } else { m2 = om2; i2 = oi2; }
                m1 = om1; i1 = oi1;
            } else if (om1 > m2) { m2 = om1; i2 = oi1; }
        }
        int tk  = (lane < 16) ? i1 : i2;
        int pos = lane & 15;
        int r0  = (tk >> 4) << 2;
        int c0  = (tk & 15) << 2;
        idx[(size_t)row * KLEN + lane] = (r0 + (pos >> 2)) * 64 + c0 + (pos & 3);
    } else {
        int bi = blockIdx.x - 64;
        int which = bi >> 5;
        int tile  = bi & 31;
        int c0 = (tile >> 2) * 32;
        int k0 = (tile & 3) * 64;
        const float* W = (which == 0) ? Wq : (which == 1) ? Wk : (which == 2) ? Wv : Wo;
        #pragma unroll
        for (int p = 0; p < 8; p++) {
            int i = p * 256 + t;
            int row = i >> 5, c = i & 31;
            sm[row][c] = W[(size_t)(k0 + row) * CDIM + c0 + c];
        }
        __syncthreads();
        #pragma unroll
        for (int p = 0; p < 4; p++) {
            int i = p * 256 + t;
            int cc = i >> 5, kp = i & 31;
            wt[(size_t)which * 32768 + (size_t)(c0 + cc) * CW + (k0 >> 1) + kp] =
                pk2(sm[2 * kp][cc], sm[2 * kp + 1][cc]);
        }
    }
}

// ---------------- fp16 QKV projection: CTA 128pix x 128cout, 512 threads ----------------
// 16 warps = 4(m)x4(n); warp tile 32m x 32n; K-chunk 32 (16 kp); pitch 20; double-buffered.
#define P_AW 20
#define P_STW (256 * P_AW)          // 5120 words per stage
#define P_GSM (2 * P_STW * 4)       // 40960 B

__global__ __launch_bounds__(512) void gemm_proj(
    const float* __restrict__ Aq, const float* __restrict__ Ak, const float* __restrict__ Av,
    const uint32_t* __restrict__ wt,
    const float* __restrict__ bq, const float* __restrict__ bk, const float* __restrict__ bv,
    uint32_t* __restrict__ oq, uint32_t* __restrict__ ok2, uint32_t* __restrict__ ov) {
    extern __shared__ uint32_t sw[];
    int m0 = blockIdx.x * 128;                 // pixels
    int c0 = blockIdx.y * 128;                 // couts
    int t = threadIdx.x;
    int lane = t & 31, w = t >> 5;             // 16 warps
    int wm = w & 3, wc = w >> 2;
    int g = lane >> 2, tq = lane & 3;

    int which = blockIdx.z >> 1, b = blockIdx.z & 1;
    const float* Ain = (which == 0) ? Aq : (which == 1) ? Ak : Av;
    const float* PA = Ain + (size_t)b * CDIM * NPIX;
    const uint32_t* PB = wt + (size_t)which * 32768;
    const float* bias = (which == 0) ? bq : (which == 1) ? bk : bv;
    uint32_t* Out = (which == 0) ? oq : (which == 1) ? ok2 : ov;
    uint32_t* outp = Out + (size_t)b * NPIX * CW;

    float acc[2][4][4];
    #pragma unroll
    for (int ms = 0; ms < 2; ms++)
        #pragma unroll
        for (int cs = 0; cs < 4; cs++)
            #pragma unroll
            for (int r = 0; r < 4; r++) acc[ms][cs][r] = 0.f;

    int mg  = t >> 4;                          // 0..31 (4 pixels each)
    int kp0 = t & 15;                          // 0..15
    float4 pa0, pa1;
    auto ldgA = [&](int kb) {
        pa0 = *(const float4*)&PA[(size_t)(kb + 2 * kp0) * NPIX + m0 + mg * 4];
        pa1 = *(const float4*)&PA[(size_t)(kb + 2 * kp0 + 1) * NPIX + m0 + mg * 4];
    };
    auto stsA = [&](int s) {
        uint32_t* A_ = sw + s * P_STW;
        const float* lo = (const float*)&pa0;
        const float* hi = (const float*)&pa1;
        #pragma unroll
        for (int i = 0; i < 4; i++)
            A_[(mg * 4 + i) * P_AW + kp0] = pk2(lo[i], hi[i]);
    };
    auto cpB = [&](int s, int kb) {
        uint32_t* B_ = sw + s * P_STW + 128 * P_AW;
        int n = t >> 2, q = t & 3;             // 128 couts x 4 cp16
        cp16(&B_[n * P_AW + q * 4], &PB[(size_t)(c0 + n) * CW + (kb >> 1) + q * 4]);
    };

    ldgA(0);
    cpB(0, 0); CP_COMMIT();
    stsA(0);

    int s = 0;
    for (int c = 0; c < 8; c++, s ^= 1) {
        CP_WAIT0();
        __syncthreads();
        bool more = (c < 7);
        if (more) {
            ldgA((c + 1) * 32);
            cpB(s ^ 1, (c + 1) * 32);
            CP_COMMIT();
        }
        uint32_t* A_ = sw + s * P_STW;
        uint32_t* B_ = A_ + 128 * P_AW;
        #pragma unroll
        for (int kc = 0; kc < 2; kc++) {
            uint32_t a[2][4], bb[4][2];
            #pragma unroll
            for (int ms = 0; ms < 2; ms++) {
                int base = (wm * 32 + ms * 16 + g) * P_AW + kc * 8 + tq;
                a[ms][0] = A_[base];
                a[ms][1] = A_[base + 8 * P_AW];
                a[ms][2] = A_[base + 4];
                a[ms][3] = A_[base + 8 * P_AW + 4];
            }
            #pragma unroll
            for (int cs = 0; cs < 4; cs++) {
                int bbase = (wc * 32 + cs * 8 + g) * P_AW + kc * 8 + tq;
                bb[cs][0] = B_[bbase];
                bb[cs][1] = B_[bbase + 4];
            }
            #pragma unroll
            for (int ms = 0; ms < 2; ms++)
                #pragma unroll
                for (int cs = 0; cs < 4; cs++)
                    mma_f16(acc[ms][cs], a[ms], bb[cs]);
        }
        if (more) stsA(s ^ 1);
    }

    #pragma unroll
    for (int ms = 0; ms < 2; ms++) {
        int r0 = m0 + wm * 32 + ms * 16 + g;
        int r1 = r0 + 8;
        #pragma unroll
        for (int cs = 0; cs < 4; cs++) {
            int c = c0 + wc * 32 + cs * 8 + 2 * tq;
            float2 b2 = *(const float2*)&bias[c];
            outp[(size_t)r0 * CW + (c >> 1)] = pk2(acc[ms][cs][0] + b2.x, acc[ms][cs][1] + b2.y);
            outp[(size_t)r1 * CW + (c >> 1)] = pk2(acc[ms][cs][2] + b2.x, acc[ms][cs][3] + b2.y);
        }
    }
}

// ---------------- fp16 output GEMM: CTA 64cout x 128pix, 512 threads, 3-stage ----------------
#define O_STW ((64 + 128) * P_AW)        // 3840 words per stage
#define O_GSM (3 * O_STW * 4)            // 46080 B

__global__ __launch_bounds__(512) void gemm_out(
    const uint32_t* __restrict__ xw, const uint32_t* __restrict__ wt,
    const float* __restrict__ bo, float* __restrict__ out) {
    extern __shared__ uint32_t sw[];
    int m0 = blockIdx.x * 64;                  // couts
    int n0 = blockIdx.y * 128;                 // pixels
    int t = threadIdx.x;
    int lane = t & 31, w = t >> 5;             // 16 warps
    int wm = w & 1, wc = w >> 1;               // 2(m) x 8(n); warp tile 32m x 16n
    int g = lane >> 2, tq = lane & 3;

    int b = blockIdx.z;
    const uint32_t* PA = wt + 3 * 32768;                 // Wo^T [cout][kp]
    const uint32_t* PB = xw + (size_t)b * NPIX * CW;     // x [pix][kp]
    float* outp = out + (size_t)b * CDIM * NPIX;

    float acc[2][2][4];
    #pragma unroll
    for (int ms = 0; ms < 2; ms++)
        #pragma unroll
        for (int cs = 0; cs < 2; cs++)
            #pragma unroll
            for (int r = 0; r < 4; r++) acc[ms][cs][r] = 0.f;

    auto cpStage = [&](int s, int kb) {
        uint32_t* A_ = sw + s * O_STW;
        uint32_t* B_ = A_ + 64 * P_AW;
        if (t < 256) {                          // A: 64 rows x 4 cp16
            int n = t >> 2, q = t & 3;
            cp16(&A_[n * P_AW + q * 4], &PA[(size_t)(m0 + n) * CW + (kb >> 1) + q * 4]);
        }
        {                                       // B: 128 rows x 4 cp16
            int n = t >> 2, q = t & 3;
            cp16(&B_[n * P_AW + q * 4], &PB[(size_t)(n0 + n) * CW + (kb >> 1) + q * 4]);
        }
    };

    cpStage(0, 0); CP_COMMIT();
    cpStage(1, 32); CP_COMMIT();

    for (int c = 0; c < 8; c++) {
        CP_WAIT1();
        __syncthreads();
        if (c + 2 < 8) { cpStage((c + 2) % 3, (c + 2) * 32); }
        CP_COMMIT();

        uint32_t* A_ = sw + (c % 3) * O_STW;
        uint32_t* B_ = A_ + 64 * P_AW;
        #pragma unroll
        for (int kc = 0; kc < 2; kc++) {
            uint32_t a[2][4], bb[2][2];
            #pragma unroll
            for (int ms = 0; ms < 2; ms++) {
                int base = (wm * 32 + ms * 16 + g) * P_AW + kc * 8 + tq;
                a[ms][0] = A_[base];
                a[ms][1] = A_[base + 8 * P_AW];
                a[ms][2] = A_[base + 4];
                a[ms][3] = A_[base + 8 * P_AW + 4];
            }
            #pragma unroll
            for (int cs = 0; cs < 2; cs++) {
                int bbase = (wc * 16 + cs * 8 + g) * P_AW + kc * 8 + tq;
                bb[cs][0] = B_[bbase];
                bb[cs][1] = B_[bbase + 4];
            }
            #pragma unroll
            for (int ms = 0; ms < 2; ms++)
                #pragma unroll
                for (int cs = 0; cs < 2; cs++)
                    mma_f16(acc[ms][cs], a[ms], bb[cs]);
        }
    }

    #pragma unroll
    for (int ms = 0; ms < 2; ms++) {
        int r0 = m0 + wm * 32 + ms * 16 + g;
        int r1 = r0 + 8;
        float b0v = bo[r0], b1v = bo[r1];
        #pragma unroll
        for (int cs = 0; cs < 2; cs++) {
            int c = n0 + wc * 16 + cs * 8 + 2 * tq;
            float2 v0 = {acc[ms][cs][0] + b0v, acc[ms][cs][1] + b0v};
            float2 v1 = {acc[ms][cs][2] + b1v, acc[ms][cs][3] + b1v};
            *(float2*)&outp[(size_t)r0 * NPIX + c] = v0;
            *(float2*)&outp[(size_t)r1 * NPIX + c] = v1;
        }
    }
}

// ---------------- fp16 tensor-core sparse attention (unchanged from R11) ----------------
#define AKW 68
#define A_KS 0
#define A_VR (32 * AKW)
#define A_QS (A_VR + 32 * AKW)
#define A_VT (A_QS + 16 * AKW)
#define A_PS (A_VT + 128 * 20)
#define A_SM ((A_PS + 4 * 320) * 4)

__global__ __launch_bounds__(128) void attn_kernel(const uint32_t* __restrict__ qw,
                                                   const uint32_t* __restrict__ kw,
                                                   const uint32_t* __restrict__ vw,
                                                   const int* __restrict__ idx,
                                                   uint32_t* __restrict__ xw) {
    int qlow = blockIdx.x;
    int b    = blockIdx.y;
    int hh   = blockIdx.z;
    extern __shared__ uint32_t smu[];
    uint32_t* Ks = smu + A_KS;
    uint32_t* Vr = smu + A_VR;
    uint32_t* Qs = smu + A_QS;
    uint32_t* Vt = smu + A_VT;
    uint32_t* Ps = smu + A_PS;
    __shared__ int sidx[KLEN];
    int t = threadIdx.x;
    int lane = t & 31, w = t >> 5;
    if (t < KLEN) sidx[t] = idx[((size_t)b * NLOW + qlow) * KLEN + t];
    __syncthreads();

    size_t bN = (size_t)b * NPIX;
    int hho = hh * 64;

    #pragma unroll
    for (int p = 0; p < 2; p++) {
        int li = p * 128 + t;
        int r = li >> 4, q4 = li & 15;
        cp16(&Qs[r * AKW + q4 * 4], &qw[(bN + qlow * 16 + r) * CW + hho + q4 * 4]);
    }
    #pragma unroll
    for (int p = 0; p < 4; p++) {
        int li = p * 128 + t;
        int r = li >> 4, q4 = li & 15;
        cp16(&Ks[r * AKW + q4 * 4], &kw[(bN + sidx[r]) * CW + hho + q4 * 4]);
    }
    CP_COMMIT();
    #pragma unroll
    for (int p = 0; p < 4; p++) {
        int li = p * 128 + t;
        int r = li >> 4, q4 = li & 15;
        cp16(&Vr[r * AKW + q4 * 4], &vw[(bN + sidx[r]) * CW + hho + q4 * 4]);
    }
    CP_COMMIT();

    int g = lane >> 2, tq = lane & 3;
    int hw = w * 16;

    CP_WAIT1();
    __syncthreads();

    uint32_t aq[2][4];
    #pragma unroll
    for (int kc = 0; kc < 2; kc++) {
        int base = g * AKW + hw + kc * 8 + tq;
        aq[kc][0] = Qs[base];
        aq[kc][1] = Qs[base + 8 * AKW];
        aq[kc][2] = Qs[base + 4];
        aq[kc][3] = Qs[base + 8 * AKW + 4];
    }

    float sc[4][4];
    #pragma unroll
    for (int nt = 0; nt < 4; nt++)
        #pragma unroll
        for (int r = 0; r < 4; r++) sc[nt][r] = 0.f;
    #pragma unroll
    for (int nt = 0; nt < 4; nt++) {
        #pragma unroll
        for (int kc = 0; kc < 2; kc++) {
            uint32_t bK[2];
            int bbase = (nt * 8 + g) * AKW + hw + kc * 8 + tq;
            bK[0] = Ks[bbase];
            bK[1] = Ks[bbase + 4];
            mma_f16(sc[nt], aq[kc], bK);
        }
    }

    const float scale = 0.17677669529663687f;
    float mx0 = -1e30f, mx1 = -1e30f;
    #pragma unroll
    for (int nt = 0; nt < 4; nt++) {
        #pragma unroll
        for (int r = 0; r < 4; r++) sc[nt][r] *= scale;
        mx0 = fmaxf(mx0, fmaxf(sc[nt][0], sc[nt][1]));
        mx1 = fmaxf(mx1, fmaxf(sc[nt][2], sc[nt][3]));
    }
    #pragma unroll
    for (int o = 1; o <= 2; o <<= 1) {
        mx0 = fmaxf(mx0, __shfl_xor_sync(0xffffffffu, mx0, o));
        mx1 = fmaxf(mx1, __shfl_xor_sync(0xffffffffu, mx1, o));
    }
    float sum0 = 0.f, sum1 = 0.f;
    #pragma unroll
    for (int nt = 0; nt < 4; nt++) {
        sc[nt][0] = __expf(sc[nt][0] - mx0);
        sc[nt][1] = __expf(sc[nt][1] - mx0);
        sc[nt][2] = __expf(sc[nt][2] - mx1);
        sc[nt][3] = __expf(sc[nt][3] - mx1);
        sum0 += sc[nt][0] + sc[nt][1];
        sum1 += sc[nt][2] + sc[nt][3];
    }
    #pragma unroll
    for (int o = 1; o <= 2; o <<= 1) {
        sum0 += __shfl_xor_sync(0xffffffffu, sum0, o);
        sum1 += __shfl_xor_sync(0xffffffffu, sum1, o);
    }

    CP_WAIT0();
    __syncthreads();

    #pragma unroll
    for (int p = 0; p < 16; p++) {
        int li = p * 128 + t;
        int d = li & 127, kp = li >> 7;
        uint32_t w0 = Vr[(2 * kp) * AKW + (d >> 1)];
        uint32_t w1 = Vr[(2 * kp + 1) * AKW + (d >> 1)];
        uint32_t sel = (d & 1) ? 0x7632u : 0x5410u;
        Vt[d * 20 + kp] = prmt(w0, w1, sel);
    }

    uint32_t* Pw = Ps + w * 320;
    #pragma unroll
    for (int nt = 0; nt < 4; nt++) {
        Pw[g * 20 + nt * 4 + tq]       = pk2(sc[nt][0], sc[nt][1]);
        Pw[(g + 8) * 20 + nt * 4 + tq] = pk2(sc[nt][2], sc[nt][3]);
    }
    __syncthreads();

    float oc[4][4];
    #pragma unroll
    for (int nt = 0; nt < 4; nt++)
        #pragma unroll
        for (int r = 0; r < 4; r++) oc[nt][r] = 0.f;
    int hd = w * 32;
    #pragma unroll
    for (int kc = 0; kc < 2; kc++) {
        uint32_t ap[4];
        ap[0] = Pw[g * 20 + kc * 8 + tq];
        ap[1] = Pw[(g + 8) * 20 + kc * 8 + tq];
        ap[2] = Pw[g * 20 + kc * 8 + tq + 4];
        ap[3] = Pw[(g + 8) * 20 + kc * 8 + tq + 4];
        #pragma unroll
        for (int nt = 0; nt < 4; nt++) {
            uint32_t bV[2];
            int bbase = (hd + nt * 8 + g) * 20 + kc * 8 + tq;
            bV[0] = Vt[bbase];
            bV[1] = Vt[bbase + 4];
            mma_f16(oc[nt], ap, bV);
        }
    }

    float inv0 = 1.f / sum0, inv1 = 1.f / sum1;
    uint32_t* x0 = xw + (bN + qlow * 16 + g) * CW + hho + hw;
    uint32_t* x1 = x0 + 8 * CW;
    #pragma unroll
    for (int nt = 0; nt < 4; nt++) {
        x0[nt * 4 + tq] = pk2(oc[nt][0] * inv0, oc[nt][1] * inv0);
        x1[nt * 4 + tq] = pk2(oc[nt][2] * inv1, oc[nt][3] * inv1);
    }
}

// ---------------- launch ----------------
extern "C" void kernel_launch(void* const* d_in, const int* in_sizes, int n_in,
                              void* d_out, int out_size) {
    const float* qh   = (const float*)d_in[0];
    const float* kh   = (const float*)d_in[1];
    const float* vh   = (const float*)d_in[2];
    const float* cmap = (const float*)d_in[3];
    const float* Wq   = (const float*)d_in[4];
    const float* bq   = (const float*)d_in[5];
    const float* Wk   = (const float*)d_in[6];
    const float* bk   = (const float*)d_in[7];
    const float* Wv   = (const float*)d_in[8];
    const float* bv   = (const float*)d_in[9];
    const float* Wo   = (const float*)d_in[10];
    const float* bo   = (const float*)d_in[11];
    float* out = (float*)d_out;

    uint32_t *pq, *pk, *pv, *px, *pw;
    int* pidx;
    cudaGetSymbolAddress((void**)&pq,   g_q);
    cudaGetSymbolAddress((void**)&pk,   g_k);
    cudaGetSymbolAddress((void**)&pv,   g_v);
    cudaGetSymbolAddress((void**)&px,   g_x);
    cudaGetSymbolAddress((void**)&pw,   g_w);
    cudaGetSymbolAddress((void**)&pidx, g_idx);

    cudaFuncSetAttribute(gemm_proj, cudaFuncAttributeMaxDynamicSharedMemorySize, P_GSM);
    cudaFuncSetAttribute(gemm_out, cudaFuncAttributeMaxDynamicSharedMemorySize, O_GSM);
    cudaFuncSetAttribute(attn_kernel, cudaFuncAttributeMaxDynamicSharedMemorySize, A_SM);

    prep_kernel<<<192, 256>>>(cmap, pidx, Wq, Wk, Wv, Wo, pw);

    dim3 gp(NPIX / 128, CDIM / 128, 6);
    gemm_proj<<<gp, 512, P_GSM>>>(qh, kh, vh, pw, bq, bk, bv, pq, pk, pv);

    attn_kernel<<<dim3(NLOW, BATCH, 2), 128, A_SM>>>(pq, pk, pv, pidx, px);

    dim3 go(CDIM / 64, NPIX / 128, BATCH);
    gemm_out<<<go, 512, O_GSM>>>(px, pw, bo, out);
}

// round 15
// speedup vs baseline: 1.1680x; 1.1680x over previous
#include <cuda_runtime.h>
#include <math.h>
#include <stdint.h>

#define NPIX 4096
#define CDIM 256
#define NLOW 256
#define KLEN 32
#define BATCH 2
#define CW 128              // words (half2) per channel row

// ---------------- scratch (no allocations allowed) ----------------
__device__ float    g_q[BATCH * NPIX * CDIM];   // proj outputs, half2 words
__device__ float    g_k[BATCH * NPIX * CDIM];
__device__ float    g_v[BATCH * NPIX * CDIM];
__device__ float    g_x[BATCH * NPIX * CDIM];
__device__ uint32_t g_fq[BATCH * NPIX * CW];    // pre-converted features, half2 [b][pix][kp]
__device__ uint32_t g_fk[BATCH * NPIX * CW];
__device__ uint32_t g_fv[BATCH * NPIX * CW];
__device__ uint32_t g_w[4 * CDIM * CDIM / 2];   // W^T as half2: [which][cout][k/2]
__device__ int      g_idx[BATCH * NLOW * KLEN];

// ---------------- helpers ----------------
__device__ __forceinline__ uint32_t pk2(float lo, float hi) {
    uint32_t r;
    asm("cvt.rn.f16x2.f32 %0, %1, %2;" : "=r"(r) : "f"(hi), "f"(lo));
    return r;
}
__device__ __forceinline__ uint32_t prmt(uint32_t a, uint32_t b, uint32_t sel) {
    uint32_t r;
    asm("prmt.b32 %0, %1, %2, %3;" : "=r"(r) : "r"(a), "r"(b), "r"(sel));
    return r;
}
__device__ __forceinline__ void mma_f16(float* c, const uint32_t* a, const uint32_t* b) {
    asm volatile(
        "mma.sync.aligned.m16n8k16.row.col.f32.f16.f16.f32 "
        "{%0,%1,%2,%3},{%4,%5,%6,%7},{%8,%9},{%0,%1,%2,%3};"
        : "+f"(c[0]), "+f"(c[1]), "+f"(c[2]), "+f"(c[3])
        : "r"(a[0]), "r"(a[1]), "r"(a[2]), "r"(a[3]), "r"(b[0]), "r"(b[1]));
}
__device__ __forceinline__ void cp16(const void* dst, const void* src) {
    uint32_t d = (uint32_t)__cvta_generic_to_shared(dst);
    asm volatile("cp.async.cg.shared.global [%0], [%1], 16;" :: "r"(d), "l"(src));
}
#define CP_COMMIT() asm volatile("cp.async.commit_group;" ::: "memory")
#define CP_WAIT0()  asm volatile("cp.async.wait_group 0;" ::: "memory")
#define CP_WAIT1()  asm volatile("cp.async.wait_group 1;" ::: "memory")

// ---------------- prep: topk (0..63) + weight transpose (64..191) + feature convert (192..959) ----------------
__global__ __launch_bounds__(256) void prep_kernel(const float* __restrict__ cmap,
                                                   int* __restrict__ idx,
                                                   const float* __restrict__ Wq,
                                                   const float* __restrict__ Wk,
                                                   const float* __restrict__ Wv,
                                                   const float* __restrict__ Wo,
                                                   uint32_t* __restrict__ wt,
                                                   const float* __restrict__ qh,
                                                   const float* __restrict__ kh,
                                                   const float* __restrict__ vh,
                                                   uint32_t* __restrict__ fq,
                                                   uint32_t* __restrict__ fk,
                                                   uint32_t* __restrict__ fv) {
    __shared__ float sm[64 * 132];             // 33.8 KB, shared by wconv/fconv branches
    int t = threadIdx.x;
    if (blockIdx.x < 64) {
        // ---- top-2 + index expansion, one warp per row ----
        int lane = t & 31;
        int row  = blockIdx.x * 8 + (t >> 5);
        const float* r = cmap + (size_t)row * NLOW;
        float m1 = -1e30f, m2 = -1e30f;
        int i1 = 0, i2 = 0;
        #pragma unroll
        for (int l = 0; l < 8; l++) {
            int j = l * 32 + lane;
            float v = r[j];
            if (v > m1)      { m2 = m1; i2 = i1; m1 = v; i1 = j; }
            else if (v > m2) { m2 = v;  i2 = j; }
        }
        #pragma unroll
        for (int off = 16; off > 0; off >>= 1) {
            float om1 = __shfl_xor_sync(0xffffffffu, m1, off);
            float om2 = __shfl_xor_sync(0xffffffffu, m2, off);
            int   oi1 = __shfl_xor_sync(0xffffffffu, i1, off);
            int   oi2 = __shfl_xor_sync(0xffffffffu, i2, off);
            if (om1 > m1) {
                if (m1 > om2) { m2 = m1; i2 = i1; } else { m2 = om2; i2 = oi2; }
                m1 = om1; i1 = oi1;
            } else if (om1 > m2) { m2 = om1; i2 = oi1; }
        }
        int tk  = (lane < 16) ? i1 : i2;
        int pos = lane & 15;
        int r0  = (tk >> 4) << 2;
        int c0  = (tk & 15) << 2;
        idx[(size_t)row * KLEN + lane] = (r0 + (pos >> 2)) * 64 + c0 + (pos & 3);
    } else if (blockIdx.x < 192) {
        // ---- weight transpose fp32 -> half2 [cout][kp] ----
        int bi = blockIdx.x - 64;
        int which = bi >> 5;
        int tile  = bi & 31;
        int c0 = (tile >> 2) * 32;
        int k0 = (tile & 3) * 64;
        const float* W = (which == 0) ? Wq : (which == 1) ? Wk : (which == 2) ? Wv : Wo;
        #pragma unroll
        for (int p = 0; p < 8; p++) {
            int i = p * 256 + t;
            int row = i >> 5, c = i & 31;
            sm[row * 33 + c] = W[(size_t)(k0 + row) * CDIM + c0 + c];
        }
        __syncthreads();
        #pragma unroll
        for (int p = 0; p < 4; p++) {
            int i = p * 256 + t;
            int cc = i >> 5, kp = i & 31;
            wt[(size_t)which * 32768 + (size_t)(c0 + cc) * CW + (k0 >> 1) + kp] =
                pk2(sm[(2 * kp) * 33 + cc], sm[(2 * kp + 1) * 33 + cc]);
        }
    } else {
        // ---- feature convert: (C, NPIX) fp32 -> [pix][kp] half2 ----
        int bi = blockIdx.x - 192;             // 0..767
        int which = bi >> 7;                   // 0..5: mat*2 + b
        int tile  = bi & 127;
        int k0 = (tile >> 5) * 64;             // k tile (64 k = 32 kp)
        int p0 = (tile & 31) * 128;            // pixel tile
        int mat = which >> 1, b = which & 1;
        const float* src = ((mat == 0) ? qh : (mat == 1) ? kh : vh) + (size_t)b * CDIM * NPIX;
        uint32_t* dst = ((mat == 0) ? fq : (mat == 1) ? fk : fv) + (size_t)b * NPIX * CW;
        // load [64 k][128 pix] tile (pitch 132 floats, float4 coalesced)
        #pragma unroll
        for (int p = 0; p < 8; p++) {
            int i = p * 256 + t;
            int row = i >> 5, c4 = (i & 31) * 4;
            *(float4*)&sm[row * 132 + c4] =
                *(const float4*)&src[(size_t)(k0 + row) * NPIX + p0 + c4];
        }
        __syncthreads();
        // write [128 pix][32 kp] half2, uint4 per thread (coalesced 128B / 8 threads)
        #pragma unroll
        for (int p = 0; p < 4; p++) {
            int i = p * 256 + t;
            int pix = i >> 3, kq = (i & 7) * 4;
            uint4 r;
            r.x = pk2(sm[(2 * kq + 0) * 132 + pix], sm[(2 * kq + 1) * 132 + pix]);
            r.y = pk2(sm[(2 * kq + 2) * 132 + pix], sm[(2 * kq + 3) * 132 + pix]);
            r.z = pk2(sm[(2 * kq + 4) * 132 + pix], sm[(2 * kq + 5) * 132 + pix]);
            r.w = pk2(sm[(2 * kq + 6) * 132 + pix], sm[(2 * kq + 7) * 132 + pix]);
            *(uint4*)&dst[(size_t)(p0 + pix) * CW + (k0 >> 1) + kq] = r;
        }
    }
}

// ---------------- fp16 QKV projection: CTA 128pix x 128cout, all-cp.async ----------------
// 8 warps = 4(m)x4? -> 4(m)x2(n); warp tile 32m x 64n; K-chunk 32 (16 kp); pitch 20.
#define P_AW 20
#define P_STW (256 * P_AW)          // 5120 words per stage (128 A rows + 128 B rows)
#define P_GSM (2 * P_STW * 4)       // 40960 B

__global__ __launch_bounds__(256) void gemm_proj(
    const uint32_t* __restrict__ fq, const uint32_t* __restrict__ fk, const uint32_t* __restrict__ fv,
    const uint32_t* __restrict__ wt,
    const float* __restrict__ bq, const float* __restrict__ bk, const float* __restrict__ bv,
    uint32_t* __restrict__ oq, uint32_t* __restrict__ ok2, uint32_t* __restrict__ ov) {
    extern __shared__ uint32_t sw[];
    int m0 = blockIdx.x * 128;                 // pixels
    int c0 = blockIdx.y * 128;                 // couts
    int t = threadIdx.x;
    int lane = t & 31, w = t >> 5;
    int wm = w & 3, wc = w >> 2;               // 4(m) x 2(n); warp tile 32m x 64n
    int g = lane >> 2, tq = lane & 3;

    int which = blockIdx.z >> 1, b = blockIdx.z & 1;
    const uint32_t* PF = ((which == 0) ? fq : (which == 1) ? fk : fv) + (size_t)b * NPIX * CW;
    const uint32_t* PB = wt + (size_t)which * 32768;
    const float* bias = (which == 0) ? bq : (which == 1) ? bk : bv;
    uint32_t* Out = (which == 0) ? oq : (which == 1) ? ok2 : ov;
    uint32_t* outp = Out + (size_t)b * NPIX * CW;

    float acc[2][8][4];
    #pragma unroll
    for (int ms = 0; ms < 2; ms++)
        #pragma unroll
        for (int cs = 0; cs < 8; cs++)
            #pragma unroll
            for (int r = 0; r < 4; r++) acc[ms][cs][r] = 0.f;

    auto cpStage = [&](int s, int kb) {
        uint32_t* A_ = sw + s * P_STW;
        uint32_t* B_ = A_ + 128 * P_AW;
        #pragma unroll
        for (int p = 0; p < 2; p++) {
            int idx = p * 256 + t;
            int n = idx >> 2, q = idx & 3;
            cp16(&A_[n * P_AW + q * 4], &PF[(size_t)(m0 + n) * CW + (kb >> 1) + q * 4]);
        }
        #pragma unroll
        for (int p = 0; p < 2; p++) {
            int idx = p * 256 + t;
            int n = idx >> 2, q = idx & 3;
            cp16(&B_[n * P_AW + q * 4], &PB[(size_t)(c0 + n) * CW + (kb >> 1) + q * 4]);
        }
    };

    cpStage(0, 0); CP_COMMIT();

    int s = 0;
    for (int c = 0; c < 8; c++, s ^= 1) {
        CP_WAIT0();
        __syncthreads();
        bool more = (c < 7);
        if (more) { cpStage(s ^ 1, (c + 1) * 32); CP_COMMIT(); }

        uint32_t* A_ = sw + s * P_STW;
        uint32_t* B_ = A_ + 128 * P_AW;
        #pragma unroll
        for (int kc = 0; kc < 2; kc++) {
            uint32_t a[2][4], bb[8][2];
            #pragma unroll
            for (int ms = 0; ms < 2; ms++) {
                int base = (wm * 32 + ms * 16 + g) * P_AW + kc * 8 + tq;
                a[ms][0] = A_[base];
                a[ms][1] = A_[base + 8 * P_AW];
                a[ms][2] = A_[base + 4];
                a[ms][3] = A_[base + 8 * P_AW + 4];
            }
            #pragma unroll
            for (int cs = 0; cs < 8; cs++) {
                int bbase = (wc * 64 + cs * 8 + g) * P_AW + kc * 8 + tq;
                bb[cs][0] = B_[bbase];
                bb[cs][1] = B_[bbase + 4];
            }
            #pragma unroll
            for (int ms = 0; ms < 2; ms++)
                #pragma unroll
                for (int cs = 0; cs < 8; cs++)
                    mma_f16(acc[ms][cs], a[ms], bb[cs]);
        }
    }

    #pragma unroll
    for (int ms = 0; ms < 2; ms++) {
        int r0 = m0 + wm * 32 + ms * 16 + g;
        int r1 = r0 + 8;
        #pragma unroll
        for (int cs = 0; cs < 8; cs++) {
            int c = c0 + wc * 64 + cs * 8 + 2 * tq;
            float2 b2 = *(const float2*)&bias[c];
            outp[(size_t)r0 * CW + (c >> 1)] = pk2(acc[ms][cs][0] + b2.x, acc[ms][cs][1] + b2.y);
            outp[(size_t)r1 * CW + (c >> 1)] = pk2(acc[ms][cs][2] + b2.x, acc[ms][cs][3] + b2.y);
        }
    }
}

// ---------------- fp16 output GEMM: CTA 64cout x 128pix (R11 exact) ----------------
#define O_STW (64 * P_AW + 128 * P_AW)   // 3840 words per stage
#define O_GSM (2 * O_STW * 4)            // 30720 B

__global__ __launch_bounds__(256) void gemm_out(
    const uint32_t* __restrict__ xw, const uint32_t* __restrict__ wt,
    const float* __restrict__ bo, float* __restrict__ out) {
    extern __shared__ uint32_t sw[];
    int m0 = blockIdx.x * 64;                  // couts
    int n0 = blockIdx.y * 128;                 // pixels
    int t = threadIdx.x;
    int lane = t & 31, w = t >> 5;
    int wm = w & 1, wc = w >> 1;
    int g = lane >> 2, tq = lane & 3;

    int b = blockIdx.z;
    const uint32_t* PA = wt + 3 * 32768;                 // Wo^T [cout][kp]
    const uint32_t* PB = xw + (size_t)b * NPIX * CW;     // x [pix][kp]
    float* outp = out + (size_t)b * CDIM * NPIX;

    float acc[2][4][4];
    #pragma unroll
    for (int ms = 0; ms < 2; ms++)
        #pragma unroll
        for (int cs = 0; cs < 4; cs++)
            #pragma unroll
            for (int r = 0; r < 4; r++) acc[ms][cs][r] = 0.f;

    auto cpStage = [&](int s, int kb) {
        uint32_t* A_ = sw + s * O_STW;
        uint32_t* B_ = A_ + 64 * P_AW;
        {
            int n = t >> 2, q = t & 3;
            cp16(&A_[n * P_AW + q * 4], &PA[(size_t)(m0 + n) * CW + (kb >> 1) + q * 4]);
        }
        #pragma unroll
        for (int p = 0; p < 2; p++) {
            int idx = p * 256 + t;
            int n = idx >> 2, q = idx & 3;
            cp16(&B_[n * P_AW + q * 4], &PB[(size_t)(n0 + n) * CW + (kb >> 1) + q * 4]);
        }
    };

    cpStage(0, 0); CP_COMMIT();

    int s = 0;
    for (int c = 0; c < 8; c++, s ^= 1) {
        CP_WAIT0();
        __syncthreads();
        bool more = (c < 7);
        if (more) { cpStage(s ^ 1, (c + 1) * 32); CP_COMMIT(); }

        uint32_t* A_ = sw + s * O_STW;
        uint32_t* B_ = A_ + 64 * P_AW;
        #pragma unroll
        for (int kc = 0; kc < 2; kc++) {
            uint32_t a[2][4], bb[4][2];
            #pragma unroll
            for (int ms = 0; ms < 2; ms++) {
                int base = (wm * 32 + ms * 16 + g) * P_AW + kc * 8 + tq;
                a[ms][0] = A_[base];
                a[ms][1] = A_[base + 8 * P_AW];
                a[ms][2] = A_[base + 4];
                a[ms][3] = A_[base + 8 * P_AW + 4];
            }
            #pragma unroll
            for (int cs = 0; cs < 4; cs++) {
                int bbase = (wc * 32 + cs * 8 + g) * P_AW + kc * 8 + tq;
                bb[cs][0] = B_[bbase];
                bb[cs][1] = B_[bbase + 4];
            }
            #pragma unroll
            for (int ms = 0; ms < 2; ms++)
                #pragma unroll
                for (int cs = 0; cs < 4; cs++)
                    mma_f16(acc[ms][cs], a[ms], bb[cs]);
        }
    }

    #pragma unroll
    for (int ms = 0; ms < 2; ms++) {
        int r0 = m0 + wm * 32 + ms * 16 + g;
        int r1 = r0 + 8;
        float b0v = bo[r0], b1v = bo[r1];
        #pragma unroll
        for (int cs = 0; cs < 4; cs++) {
            int c = n0 + wc * 32 + cs * 8 + 2 * tq;
            float2 v0 = {acc[ms][cs][0] + b0v, acc[ms][cs][1] + b0v};
            float2 v1 = {acc[ms][cs][2] + b1v, acc[ms][cs][3] + b1v};
            *(float2*)&outp[(size_t)r0 * NPIX + c] = v0;
            *(float2*)&outp[(size_t)r1 * NPIX + c] = v1;
        }
    }
}

// ---------------- fp16 tensor-core sparse attention (R11 exact) ----------------
#define AKW 68
#define A_KS 0
#define A_VR (32 * AKW)
#define A_QS (A_VR + 32 * AKW)
#define A_VT (A_QS + 16 * AKW)
#define A_PS (A_VT + 128 * 20)
#define A_SM ((A_PS + 4 * 320) * 4)

__global__ __launch_bounds__(128) void attn_kernel(const uint32_t* __restrict__ qw,
                                                   const uint32_t* __restrict__ kw,
                                                   const uint32_t* __restrict__ vw,
                                                   const int* __restrict__ idx,
                                                   uint32_t* __restrict__ xw) {
    int qlow = blockIdx.x;
    int b    = blockIdx.y;
    int hh   = blockIdx.z;
    extern __shared__ uint32_t smu[];
    uint32_t* Ks = smu + A_KS;
    uint32_t* Vr = smu + A_VR;
    uint32_t* Qs = smu + A_QS;
    uint32_t* Vt = smu + A_VT;
    uint32_t* Ps = smu + A_PS;
    __shared__ int sidx[KLEN];
    int t = threadIdx.x;
    int lane = t & 31, w = t >> 5;
    if (t < KLEN) sidx[t] = idx[((size_t)b * NLOW + qlow) * KLEN + t];
    __syncthreads();

    size_t bN = (size_t)b * NPIX;
    int hho = hh * 64;

    #pragma unroll
    for (int p = 0; p < 2; p++) {
        int li = p * 128 + t;
        int r = li >> 4, q4 = li & 15;
        cp16(&Qs[r * AKW + q4 * 4], &qw[(bN + qlow * 16 + r) * CW + hho + q4 * 4]);
    }
    #pragma unroll
    for (int p = 0; p < 4; p++) {
        int li = p * 128 + t;
        int r = li >> 4, q4 = li & 15;
        cp16(&Ks[r * AKW + q4 * 4], &kw[(bN + sidx[r]) * CW + hho + q4 * 4]);
    }
    CP_COMMIT();
    #pragma unroll
    for (int p = 0; p < 4; p++) {
        int li = p * 128 + t;
        int r = li >> 4, q4 = li & 15;
        cp16(&Vr[r * AKW + q4 * 4], &vw[(bN + sidx[r]) * CW + hho + q4 * 4]);
    }
    CP_COMMIT();

    int g = lane >> 2, tq = lane & 3;
    int hw = w * 16;

    CP_WAIT1();
    __syncthreads();

    uint32_t aq[2][4];
    #pragma unroll
    for (int kc = 0; kc < 2; kc++) {
        int base = g * AKW + hw + kc * 8 + tq;
        aq[kc][0] = Qs[base];
        aq[kc][1] = Qs[base + 8 * AKW];
        aq[kc][2] = Qs[base + 4];
        aq[kc][3] = Qs[base + 8 * AKW + 4];
    }

    float sc[4][4];
    #pragma unroll
    for (int nt = 0; nt < 4; nt++)
        #pragma unroll
        for (int r = 0; r < 4; r++) sc[nt][r] = 0.f;
    #pragma unroll
    for (int nt = 0; nt < 4; nt++) {
        #pragma unroll
        for (int kc = 0; kc < 2; kc++) {
            uint32_t bK[2];
            int bbase = (nt * 8 + g) * AKW + hw + kc * 8 + tq;
            bK[0] = Ks[bbase];
            bK[1] = Ks[bbase + 4];
            mma_f16(sc[nt], aq[kc], bK);
        }
    }

    const float scale = 0.17677669529663687f;
    float mx0 = -1e30f, mx1 = -1e30f;
    #pragma unroll
    for (int nt = 0; nt < 4; nt++) {
        #pragma unroll
        for (int r = 0; r < 4; r++) sc[nt][r] *= scale;
        mx0 = fmaxf(mx0, fmaxf(sc[nt][0], sc[nt][1]));
        mx1 = fmaxf(mx1, fmaxf(sc[nt][2], sc[nt][3]));
    }
    #pragma unroll
    for (int o = 1; o <= 2; o <<= 1) {
        mx0 = fmaxf(mx0, __shfl_xor_sync(0xffffffffu, mx0, o));
        mx1 = fmaxf(mx1, __shfl_xor_sync(0xffffffffu, mx1, o));
    }
    float sum0 = 0.f, sum1 = 0.f;
    #pragma unroll
    for (int nt = 0; nt < 4; nt++) {
        sc[nt][0] = __expf(sc[nt][0] - mx0);
        sc[nt][1] = __expf(sc[nt][1] - mx0);
        sc[nt][2] = __expf(sc[nt][2] - mx1);
        sc[nt][3] = __expf(sc[nt][3] - mx1);
        sum0 += sc[nt][0] + sc[nt][1];
        sum1 += sc[nt][2] + sc[nt][3];
    }
    #pragma unroll
    for (int o = 1; o <= 2; o <<= 1) {
        sum0 += __shfl_xor_sync(0xffffffffu, sum0, o);
        sum1 += __shfl_xor_sync(0xffffffffu, sum1, o);
    }

    CP_WAIT0();
    __syncthreads();

    #pragma unroll
    for (int p = 0; p < 16; p++) {
        int li = p * 128 + t;
        int d = li & 127, kp = li >> 7;
        uint32_t w0 = Vr[(2 * kp) * AKW + (d >> 1)];
        uint32_t w1 = Vr[(2 * kp + 1) * AKW + (d >> 1)];
        uint32_t sel = (d & 1) ? 0x7632u : 0x5410u;
        Vt[d * 20 + kp] = prmt(w0, w1, sel);
    }

    uint32_t* Pw = Ps + w * 320;
    #pragma unroll
    for (int nt = 0; nt < 4; nt++) {
        Pw[g * 20 + nt * 4 + tq]       = pk2(sc[nt][0], sc[nt][1]);
        Pw[(g + 8) * 20 + nt * 4 + tq] = pk2(sc[nt][2], sc[nt][3]);
    }
    __syncthreads();

    float oc[4][4];
    #pragma unroll
    for (int nt = 0; nt < 4; nt++)
        #pragma unroll
        for (int r = 0; r < 4; r++) oc[nt][r] = 0.f;
    int hd = w * 32;
    #pragma unroll
    for (int kc = 0; kc < 2; kc++) {
        uint32_t ap[4];
        ap[0] = Pw[g * 20 + kc * 8 + tq];
        ap[1] = Pw[(g + 8) * 20 + kc * 8 + tq];
        ap[2] = Pw[g * 20 + kc * 8 + tq + 4];
        ap[3] = Pw[(g + 8) * 20 + kc * 8 + tq + 4];
        #pragma unroll
        for (int nt = 0; nt < 4; nt++) {
            uint32_t bV[2];
            int bbase = (hd + nt * 8 + g) * 20 + kc * 8 + tq;
            bV[0] = Vt[bbase];
            bV[1] = Vt[bbase + 4];
            mma_f16(oc[nt], ap, bV);
        }
    }

    float inv0 = 1.f / sum0, inv1 = 1.f / sum1;
    uint32_t* x0 = xw + (bN + qlow * 16 + g) * CW + hho + hw;
    uint32_t* x1 = x0 + 8 * CW;
    #pragma unroll
    for (int nt = 0; nt < 4; nt++) {
        x0[nt * 4 + tq] = pk2(oc[nt][0] * inv0, oc[nt][1] * inv0);
        x1[nt * 4 + tq] = pk2(oc[nt][2] * inv1, oc[nt][3] * inv1);
    }
}

// ---------------- launch ----------------
extern "C" void kernel_launch(void* const* d_in, const int* in_sizes, int n_in,
                              void* d_out, int out_size) {
    const float* qh   = (const float*)d_in[0];
    const float* kh   = (const float*)d_in[1];
    const float* vh   = (const float*)d_in[2];
    const float* cmap = (const float*)d_in[3];
    const float* Wq   = (const float*)d_in[4];
    const float* bq   = (const float*)d_in[5];
    const float* Wk   = (const float*)d_in[6];
    const float* bk   = (const float*)d_in[7];
    const float* Wv   = (const float*)d_in[8];
    const float* bv   = (const float*)d_in[9];
    const float* Wo   = (const float*)d_in[10];
    const float* bo   = (const float*)d_in[11];
    float* out = (float*)d_out;

    uint32_t *pq, *pk, *pv, *px, *pw, *pfq, *pfk, *pfv;
    int* pidx;
    cudaGetSymbolAddress((void**)&pq,   g_q);
    cudaGetSymbolAddress((void**)&pk,   g_k);
    cudaGetSymbolAddress((void**)&pv,   g_v);
    cudaGetSymbolAddress((void**)&px,   g_x);
    cudaGetSymbolAddress((void**)&pw,   g_w);
    cudaGetSymbolAddress((void**)&pfq,  g_fq);
    cudaGetSymbolAddress((void**)&pfk,  g_fk);
    cudaGetSymbolAddress((void**)&pfv,  g_fv);
    cudaGetSymbolAddress((void**)&pidx, g_idx);

    cudaFuncSetAttribute(gemm_proj, cudaFuncAttributeMaxDynamicSharedMemorySize, P_GSM);
    cudaFuncSetAttribute(gemm_out, cudaFuncAttributeMaxDynamicSharedMemorySize, O_GSM);
    cudaFuncSetAttribute(attn_kernel, cudaFuncAttributeMaxDynamicSharedMemorySize, A_SM);

    prep_kernel<<<960, 256>>>(cmap, pidx, Wq, Wk, Wv, Wo, pw,
                              qh, kh, vh, pfq, pfk, pfv);

    dim3 gp(NPIX / 128, CDIM / 128, 6);
    gemm_proj<<<gp, 256, P_GSM>>>(pfq, pfk, pfv, pw, bq, bk, bv, pq, pk, pv);

    attn_kernel<<<dim3(NLOW, BATCH, 2), 128, A_SM>>>(pq, pk, pv, pidx, px);

    dim3 go(CDIM / 64, NPIX / 128, BATCH);
    gemm_out<<<go, 256, O_GSM>>>(px, pw, bo, out);
}

// round 16
// speedup vs baseline: 1.2303x; 1.0534x over previous
#include <cuda_runtime.h>
#include <math.h>
#include <stdint.h>

#define NPIX 4096
#define CDIM 256
#define NLOW 256
#define KLEN 32
#define BATCH 2
#define CW 128              // words (half2) per channel row

// ---------------- scratch (no allocations allowed) ----------------
__device__ float    g_q[BATCH * NPIX * CDIM];   // proj outputs, half2 words
__device__ float    g_k[BATCH * NPIX * CDIM];
__device__ float    g_v[BATCH * NPIX * CDIM];
__device__ float    g_x[BATCH * NPIX * CDIM];
__device__ uint32_t g_fq[BATCH * NPIX * CW];    // pre-converted features, half2 [b][pix][kp]
__device__ uint32_t g_fk[BATCH * NPIX * CW];
__device__ uint32_t g_fv[BATCH * NPIX * CW];
__device__ uint32_t g_w[4 * CDIM * CDIM / 2];   // W^T as half2: [which][cout][k/2]
__device__ int      g_idx[BATCH * NLOW * KLEN];

// ---------------- helpers ----------------
__device__ __forceinline__ uint32_t pk2(float lo, float hi) {
    uint32_t r;
    asm("cvt.rn.f16x2.f32 %0, %1, %2;" : "=r"(r) : "f"(hi), "f"(lo));
    return r;
}
__device__ __forceinline__ uint32_t prmt(uint32_t a, uint32_t b, uint32_t sel) {
    uint32_t r;
    asm("prmt.b32 %0, %1, %2, %3;" : "=r"(r) : "r"(a), "r"(b), "r"(sel));
    return r;
}
__device__ __forceinline__ void mma_f16(float* c, const uint32_t* a, const uint32_t* b) {
    asm volatile(
        "mma.sync.aligned.m16n8k16.row.col.f32.f16.f16.f32 "
        "{%0,%1,%2,%3},{%4,%5,%6,%7},{%8,%9},{%0,%1,%2,%3};"
        : "+f"(c[0]), "+f"(c[1]), "+f"(c[2]), "+f"(c[3])
        : "r"(a[0]), "r"(a[1]), "r"(a[2]), "r"(a[3]), "r"(b[0]), "r"(b[1]));
}
__device__ __forceinline__ void cp16(const void* dst, const void* src) {
    uint32_t d = (uint32_t)__cvta_generic_to_shared(dst);
    asm volatile("cp.async.cg.shared.global [%0], [%1], 16;" :: "r"(d), "l"(src));
}
#define CP_COMMIT() asm volatile("cp.async.commit_group;" ::: "memory")
#define CP_WAIT0()  asm volatile("cp.async.wait_group 0;" ::: "memory")
#define CP_WAIT1()  asm volatile("cp.async.wait_group 1;" ::: "memory")

// ---------------- prep: topk (0..63) + weight transpose (64..191) + feature convert (192..959) ----------------
__global__ __launch_bounds__(256) void prep_kernel(const float* __restrict__ cmap,
                                                   int* __restrict__ idx,
                                                   const float* __restrict__ Wq,
                                                   const float* __restrict__ Wk,
                                                   const float* __restrict__ Wv,
                                                   const float* __restrict__ Wo,
                                                   uint32_t* __restrict__ wt,
                                                   const float* __restrict__ qh,
                                                   const float* __restrict__ kh,
                                                   const float* __restrict__ vh,
                                                   uint32_t* __restrict__ fq,
                                                   uint32_t* __restrict__ fk,
                                                   uint32_t* __restrict__ fv) {
    __shared__ float sm[64 * 132];
    int t = threadIdx.x;
    if (blockIdx.x < 64) {
        int lane = t & 31;
        int row  = blockIdx.x * 8 + (t >> 5);
        const float* r = cmap + (size_t)row * NLOW;
        float m1 = -1e30f, m2 = -1e30f;
        int i1 = 0, i2 = 0;
        #pragma unroll
        for (int l = 0; l < 8; l++) {
            int j = l * 32 + lane;
            float v = r[j];
            if (v > m1)      { m2 = m1; i2 = i1; m1 = v; i1 = j; }
            else if (v > m2) { m2 = v;  i2 = j; }
        }
        #pragma unroll
        for (int off = 16; off > 0; off >>= 1) {
            float om1 = __shfl_xor_sync(0xffffffffu, m1, off);
            float om2 = __shfl_xor_sync(0xffffffffu, m2, off);
            int   oi1 = __shfl_xor_sync(0xffffffffu, i1, off);
            int   oi2 = __shfl_xor_sync(0xffffffffu, i2, off);
            if (om1 > m1) {
                if (m1 > om2) { m2 = m1; i2 = i1; } else { m2 = om2; i2 = oi2; }
                m1 = om1; i1 = oi1;
            } else if (om1 > m2) { m2 = om1; i2 = oi1; }
        }
        int tk  = (lane < 16) ? i1 : i2;
        int pos = lane & 15;
        int r0  = (tk >> 4) << 2;
        int c0  = (tk & 15) << 2;
        idx[(size_t)row * KLEN + lane] = (r0 + (pos >> 2)) * 64 + c0 + (pos & 3);
    } else if (blockIdx.x < 192) {
        int bi = blockIdx.x - 64;
        int which = bi >> 5;
        int tile  = bi & 31;
        int c0 = (tile >> 2) * 32;
        int k0 = (tile & 3) * 64;
        const float* W = (which == 0) ? Wq : (which == 1) ? Wk : (which == 2) ? Wv : Wo;
        #pragma unroll
        for (int p = 0; p < 8; p++) {
            int i = p * 256 + t;
            int row = i >> 5, c = i & 31;
            sm[row * 33 + c] = W[(size_t)(k0 + row) * CDIM + c0 + c];
        }
        __syncthreads();
        #pragma unroll
        for (int p = 0; p < 4; p++) {
            int i = p * 256 + t;
            int cc = i >> 5, kp = i & 31;
            wt[(size_t)which * 32768 + (size_t)(c0 + cc) * CW + (k0 >> 1) + kp] =
                pk2(sm[(2 * kp) * 33 + cc], sm[(2 * kp + 1) * 33 + cc]);
        }
    } else {
        int bi = blockIdx.x - 192;             // 0..767
        int which = bi >> 7;
        int tile  = bi & 127;
        int k0 = (tile >> 5) * 64;
        int p0 = (tile & 31) * 128;
        int mat = which >> 1, b = which & 1;
        const float* src = ((mat == 0) ? qh : (mat == 1) ? kh : vh) + (size_t)b * CDIM * NPIX;
        uint32_t* dst = ((mat == 0) ? fq : (mat == 1) ? fk : fv) + (size_t)b * NPIX * CW;
        #pragma unroll
        for (int p = 0; p < 8; p++) {
            int i = p * 256 + t;
            int row = i >> 5, c4 = (i & 31) * 4;
            *(float4*)&sm[row * 132 + c4] =
                *(const float4*)&src[(size_t)(k0 + row) * NPIX + p0 + c4];
        }
        __syncthreads();
        #pragma unroll
        for (int p = 0; p < 4; p++) {
            int i = p * 256 + t;
            int pix = i >> 3, kq = (i & 7) * 4;
            uint4 r;
            r.x = pk2(sm[(2 * kq + 0) * 132 + pix], sm[(2 * kq + 1) * 132 + pix]);
            r.y = pk2(sm[(2 * kq + 2) * 132 + pix], sm[(2 * kq + 3) * 132 + pix]);
            r.z = pk2(sm[(2 * kq + 4) * 132 + pix], sm[(2 * kq + 5) * 132 + pix]);
            r.w = pk2(sm[(2 * kq + 6) * 132 + pix], sm[(2 * kq + 7) * 132 + pix]);
            *(uint4*)&dst[(size_t)(p0 + pix) * CW + (k0 >> 1) + kq] = r;
        }
    }
}

// ---------------- fp16 QKV projection: CTA 128pix x 128cout, K-chunk 64 ----------------
// 8 warps = 4(m)x2(n); warp tile 32m x 64n; 4 chunks of 64 k (32 kp); pitch 36.
#define P_AW 36
#define P_STW (256 * P_AW)          // 9216 words per stage
#define P_GSM (2 * P_STW * 4)       // 73728 B

__global__ __launch_bounds__(256) void gemm_proj(
    const uint32_t* __restrict__ fq, const uint32_t* __restrict__ fk, const uint32_t* __restrict__ fv,
    const uint32_t* __restrict__ wt,
    const float* __restrict__ bq, const float* __restrict__ bk, const float* __restrict__ bv,
    uint32_t* __restrict__ oq, uint32_t* __restrict__ ok2, uint32_t* __restrict__ ov) {
    extern __shared__ uint32_t sw[];
    int m0 = blockIdx.x * 128;                 // pixels
    int c0 = blockIdx.y * 128;                 // couts
    int t = threadIdx.x;
    int lane = t & 31, w = t >> 5;
    int wm = w & 3, wc = w >> 2;
    int g = lane >> 2, tq = lane & 3;

    int which = blockIdx.z >> 1, b = blockIdx.z & 1;
    const uint32_t* PF = ((which == 0) ? fq : (which == 1) ? fk : fv) + (size_t)b * NPIX * CW;
    const uint32_t* PB = wt + (size_t)which * 32768;
    const float* bias = (which == 0) ? bq : (which == 1) ? bk : bv;
    uint32_t* Out = (which == 0) ? oq : (which == 1) ? ok2 : ov;
    uint32_t* outp = Out + (size_t)b * NPIX * CW;

    float acc[2][8][4];
    #pragma unroll
    for (int ms = 0; ms < 2; ms++)
        #pragma unroll
        for (int cs = 0; cs < 8; cs++)
            #pragma unroll
            for (int r = 0; r < 4; r++) acc[ms][cs][r] = 0.f;

    auto cpStage = [&](int s, int kb) {        // kb in k units (64 per chunk)
        uint32_t* A_ = sw + s * P_STW;
        uint32_t* B_ = A_ + 128 * P_AW;
        #pragma unroll
        for (int p = 0; p < 4; p++) {
            int idx = p * 256 + t;
            int n = idx >> 3, q = idx & 7;
            cp16(&A_[n * P_AW + q * 4], &PF[(size_t)(m0 + n) * CW + (kb >> 1) + q * 4]);
        }
        #pragma unroll
        for (int p = 0; p < 4; p++) {
            int idx = p * 256 + t;
            int n = idx >> 3, q = idx & 7;
            cp16(&B_[n * P_AW + q * 4], &PB[(size_t)(c0 + n) * CW + (kb >> 1) + q * 4]);
        }
    };

    cpStage(0, 0); CP_COMMIT();

    int s = 0;
    for (int c = 0; c < 4; c++, s ^= 1) {
        CP_WAIT0();
        __syncthreads();
        bool more = (c < 3);
        if (more) { cpStage(s ^ 1, (c + 1) * 64); CP_COMMIT(); }

        uint32_t* A_ = sw + s * P_STW;
        uint32_t* B_ = A_ + 128 * P_AW;
        #pragma unroll
        for (int kc = 0; kc < 4; kc++) {
            uint32_t a[2][4], bb[8][2];
            #pragma unroll
            for (int ms = 0; ms < 2; ms++) {
                int base = (wm * 32 + ms * 16 + g) * P_AW + kc * 8 + tq;
                a[ms][0] = A_[base];
                a[ms][1] = A_[base + 8 * P_AW];
                a[ms][2] = A_[base + 4];
                a[ms][3] = A_[base + 8 * P_AW + 4];
            }
            #pragma unroll
            for (int cs = 0; cs < 8; cs++) {
                int bbase = (wc * 64 + cs * 8 + g) * P_AW + kc * 8 + tq;
                bb[cs][0] = B_[bbase];
                bb[cs][1] = B_[bbase + 4];
            }
            #pragma unroll
            for (int ms = 0; ms < 2; ms++)
                #pragma unroll
                for (int cs = 0; cs < 8; cs++)
                    mma_f16(acc[ms][cs], a[ms], bb[cs]);
        }
    }

    #pragma unroll
    for (int ms = 0; ms < 2; ms++) {
        int r0 = m0 + wm * 32 + ms * 16 + g;
        int r1 = r0 + 8;
        #pragma unroll
        for (int cs = 0; cs < 8; cs++) {
            int c = c0 + wc * 64 + cs * 8 + 2 * tq;
            float2 b2 = *(const float2*)&bias[c];
            outp[(size_t)r0 * CW + (c >> 1)] = pk2(acc[ms][cs][0] + b2.x, acc[ms][cs][1] + b2.y);
            outp[(size_t)r1 * CW + (c >> 1)] = pk2(acc[ms][cs][2] + b2.x, acc[ms][cs][3] + b2.y);
        }
    }
}

// ---------------- fp16 output GEMM: CTA 64cout x 128pix, K-chunk 64 ----------------
#define O_STW ((64 + 128) * P_AW)        // 6912 words per stage
#define O_GSM (2 * O_STW * 4)            // 55296 B

__global__ __launch_bounds__(256) void gemm_out(
    const uint32_t* __restrict__ xw, const uint32_t* __restrict__ wt,
    const float* __restrict__ bo, float* __restrict__ out) {
    extern __shared__ uint32_t sw[];
    int m0 = blockIdx.x * 64;                  // couts
    int n0 = blockIdx.y * 128;                 // pixels
    int t = threadIdx.x;
    int lane = t & 31, w = t >> 5;
    int wm = w & 1, wc = w >> 1;
    int g = lane >> 2, tq = lane & 3;

    int b = blockIdx.z;
    const uint32_t* PA = wt + 3 * 32768;                 // Wo^T [cout][kp]
    const uint32_t* PB = xw + (size_t)b * NPIX * CW;     // x [pix][kp]
    float* outp = out + (size_t)b * CDIM * NPIX;

    float acc[2][4][4];
    #pragma unroll
    for (int ms = 0; ms < 2; ms++)
        #pragma unroll
        for (int cs = 0; cs < 4; cs++)
            #pragma unroll
            for (int r = 0; r < 4; r++) acc[ms][cs][r] = 0.f;

    auto cpStage = [&](int s, int kb) {
        uint32_t* A_ = sw + s * O_STW;
        uint32_t* B_ = A_ + 64 * P_AW;
        #pragma unroll
        for (int p = 0; p < 2; p++) {          // A: 64 rows x 8 cp16 = 512
            int idx = p * 256 + t;
            int n = idx >> 3, q = idx & 7;
            cp16(&A_[n * P_AW + q * 4], &PA[(size_t)(m0 + n) * CW + (kb >> 1) + q * 4]);
        }
        #pragma unroll
        for (int p = 0; p < 4; p++) {          // B: 128 rows x 8 cp16 = 1024
            int idx = p * 256 + t;
            int n = idx >> 3, q = idx & 7;
            cp16(&B_[n * P_AW + q * 4], &PB[(size_t)(n0 + n) * CW + (kb >> 1) + q * 4]);
        }
    };

    cpStage(0, 0); CP_COMMIT();

    int s = 0;
    for (int c = 0; c < 4; c++, s ^= 1) {
        CP_WAIT0();
        __syncthreads();
        bool more = (c < 3);
        if (more) { cpStage(s ^ 1, (c + 1) * 64); CP_COMMIT(); }

        uint32_t* A_ = sw + s * O_STW;
        uint32_t* B_ = A_ + 64 * P_AW;
        #pragma unroll
        for (int kc = 0; kc < 4; kc++) {
            uint32_t a[2][4], bb[4][2];
            #pragma unroll
            for (int ms = 0; ms < 2; ms++) {
                int base = (wm * 32 + ms * 16 + g) * P_AW + kc * 8 + tq;
                a[ms][0] = A_[base];
                a[ms][1] = A_[base + 8 * P_AW];
                a[ms][2] = A_[base + 4];
                a[ms][3] = A_[base + 8 * P_AW + 4];
            }
            #pragma unroll
            for (int cs = 0; cs < 4; cs++) {
                int bbase = (wc * 32 + cs * 8 + g) * P_AW + kc * 8 + tq;
                bb[cs][0] = B_[bbase];
                bb[cs][1] = B_[bbase + 4];
            }
            #pragma unroll
            for (int ms = 0; ms < 2; ms++)
                #pragma unroll
                for (int cs = 0; cs < 4; cs++)
                    mma_f16(acc[ms][cs], a[ms], bb[cs]);
        }
    }

    #pragma unroll
    for (int ms = 0; ms < 2; ms++) {
        int r0 = m0 + wm * 32 + ms * 16 + g;
        int r1 = r0 + 8;
        float b0v = bo[r0], b1v = bo[r1];
        #pragma unroll
        for (int cs = 0; cs < 4; cs++) {
            int c = n0 + wc * 32 + cs * 8 + 2 * tq;
            float2 v0 = {acc[ms][cs][0] + b0v, acc[ms][cs][1] + b0v};
            float2 v1 = {acc[ms][cs][2] + b1v, acc[ms][cs][3] + b1v};
            *(float2*)&outp[(size_t)r0 * NPIX + c] = v0;
            *(float2*)&outp[(size_t)r1 * NPIX + c] = v1;
        }
    }
}

// ---------------- fp16 tensor-core sparse attention (R11 exact) ----------------
#define AKW 68
#define A_KS 0
#define A_VR (32 * AKW)
#define A_QS (A_VR + 32 * AKW)
#define A_VT (A_QS + 16 * AKW)
#define A_PS (A_VT + 128 * 20)
#define A_SM ((A_PS + 4 * 320) * 4)

__global__ __launch_bounds__(128) void attn_kernel(const uint32_t* __restrict__ qw,
                                                   const uint32_t* __restrict__ kw,
                                                   const uint32_t* __restrict__ vw,
                                                   const int* __restrict__ idx,
                                                   uint32_t* __restrict__ xw) {
    int qlow = blockIdx.x;
    int b    = blockIdx.y;
    int hh   = blockIdx.z;
    extern __shared__ uint32_t smu[];
    uint32_t* Ks = smu + A_KS;
    uint32_t* Vr = smu + A_VR;
    uint32_t* Qs = smu + A_QS;
    uint32_t* Vt = smu + A_VT;
    uint32_t* Ps = smu + A_PS;
    __shared__ int sidx[KLEN];
    int t = threadIdx.x;
    int lane = t & 31, w = t >> 5;
    if (t < KLEN) sidx[t] = idx[((size_t)b * NLOW + qlow) * KLEN + t];
    __syncthreads();

    size_t bN = (size_t)b * NPIX;
    int hho = hh * 64;

    #pragma unroll
    for (int p = 0; p < 2; p++) {
        int li = p * 128 + t;
        int r = li >> 4, q4 = li & 15;
        cp16(&Qs[r * AKW + q4 * 4], &qw[(bN + qlow * 16 + r) * CW + hho + q4 * 4]);
    }
    #pragma unroll
    for (int p = 0; p < 4; p++) {
        int li = p * 128 + t;
        int r = li >> 4, q4 = li & 15;
        cp16(&Ks[r * AKW + q4 * 4], &kw[(bN + sidx[r]) * CW + hho + q4 * 4]);
    }
    CP_COMMIT();
    #pragma unroll
    for (int p = 0; p < 4; p++) {
        int li = p * 128 + t;
        int r = li >> 4, q4 = li & 15;
        cp16(&Vr[r * AKW + q4 * 4], &vw[(bN + sidx[r]) * CW + hho + q4 * 4]);
    }
    CP_COMMIT();

    int g = lane >> 2, tq = lane & 3;
    int hw = w * 16;

    CP_WAIT1();
    __syncthreads();

    uint32_t aq[2][4];
    #pragma unroll
    for (int kc = 0; kc < 2; kc++) {
        int base = g * AKW + hw + kc * 8 + tq;
        aq[kc][0] = Qs[base];
        aq[kc][1] = Qs[base + 8 * AKW];
        aq[kc][2] = Qs[base + 4];
        aq[kc][3] = Qs[base + 8 * AKW + 4];
    }

    float sc[4][4];
    #pragma unroll
    for (int nt = 0; nt < 4; nt++)
        #pragma unroll
        for (int r = 0; r < 4; r++) sc[nt][r] = 0.f;
    #pragma unroll
    for (int nt = 0; nt < 4; nt++) {
        #pragma unroll
        for (int kc = 0; kc < 2; kc++) {
            uint32_t bK[2];
            int bbase = (nt * 8 + g) * AKW + hw + kc * 8 + tq;
            bK[0] = Ks[bbase];
            bK[1] = Ks[bbase + 4];
            mma_f16(sc[nt], aq[kc], bK);
        }
    }

    const float scale = 0.17677669529663687f;
    float mx0 = -1e30f, mx1 = -1e30f;
    #pragma unroll
    for (int nt = 0; nt < 4; nt++) {
        #pragma unroll
        for (int r = 0; r < 4; r++) sc[nt][r] *= scale;
        mx0 = fmaxf(mx0, fmaxf(sc[nt][0], sc[nt][1]));
        mx1 = fmaxf(mx1, fmaxf(sc[nt][2], sc[nt][3]));
    }
    #pragma unroll
    for (int o = 1; o <= 2; o <<= 1) {
        mx0 = fmaxf(mx0, __shfl_xor_sync(0xffffffffu, mx0, o));
        mx1 = fmaxf(mx1, __shfl_xor_sync(0xffffffffu, mx1, o));
    }
    float sum0 = 0.f, sum1 = 0.f;
    #pragma unroll
    for (int nt = 0; nt < 4; nt++) {
        sc[nt][0] = __expf(sc[nt][0] - mx0);
        sc[nt][1] = __expf(sc[nt][1] - mx0);
        sc[nt][2] = __expf(sc[nt][2] - mx1);
        sc[nt][3] = __expf(sc[nt][3] - mx1);
        sum0 += sc[nt][0] + sc[nt][1];
        sum1 += sc[nt][2] + sc[nt][3];
    }
    #pragma unroll
    for (int o = 1; o <= 2; o <<= 1) {
        sum0 += __shfl_xor_sync(0xffffffffu, sum0, o);
        sum1 += __shfl_xor_sync(0xffffffffu, sum1, o);
    }

    CP_WAIT0();
    __syncthreads();

    #pragma unroll
    for (int p = 0; p < 16; p++) {
        int li = p * 128 + t;
        int d = li & 127, kp = li >> 7;
        uint32_t w0 = Vr[(2 * kp) * AKW + (d >> 1)];
        uint32_t w1 = Vr[(2 * kp + 1) * AKW + (d >> 1)];
        uint32_t sel = (d & 1) ? 0x7632u : 0x5410u;
        Vt[d * 20 + kp] = prmt(w0, w1, sel);
    }

    uint32_t* Pw = Ps + w * 320;
    #pragma unroll
    for (int nt = 0; nt < 4; nt++) {
        Pw[g * 20 + nt * 4 + tq]       = pk2(sc[nt][0], sc[nt][1]);
        Pw[(g + 8) * 20 + nt * 4 + tq] = pk2(sc[nt][2], sc[nt][3]);
    }
    __syncthreads();

    float oc[4][4];
    #pragma unroll
    for (int nt = 0; nt < 4; nt++)
        #pragma unroll
        for (int r = 0; r < 4; r++) oc[nt][r] = 0.f;
    int hd = w * 32;
    #pragma unroll
    for (int kc = 0; kc < 2; kc++) {
        uint32_t ap[4];
        ap[0] = Pw[g * 20 + kc * 8 + tq];
        ap[1] = Pw[(g + 8) * 20 + kc * 8 + tq];
        ap[2] = Pw[g * 20 + kc * 8 + tq + 4];
        ap[3] = Pw[(g + 8) * 20 + kc * 8 + tq + 4];
        #pragma unroll
        for (int nt = 0; nt < 4; nt++) {
            uint32_t bV[2];
            int bbase = (hd + nt * 8 + g) * 20 + kc * 8 + tq;
            bV[0] = Vt[bbase];
            bV[1] = Vt[bbase + 4];
            mma_f16(oc[nt], ap, bV);
        }
    }

    float inv0 = 1.f / sum0, inv1 = 1.f / sum1;
    uint32_t* x0 = xw + (bN + qlow * 16 + g) * CW + hho + hw;
    uint32_t* x1 = x0 + 8 * CW;
    #pragma unroll
    for (int nt = 0; nt < 4; nt++) {
        x0[nt * 4 + tq] = pk2(oc[nt][0] * inv0, oc[nt][1] * inv0);
        x1[nt * 4 + tq] = pk2(oc[nt][2] * inv1, oc[nt][3] * inv1);
    }
}

// ---------------- launch ----------------
extern "C" void kernel_launch(void* const* d_in, const int* in_sizes, int n_in,
                              void* d_out, int out_size) {
    const float* qh   = (const float*)d_in[0];
    const float* kh   = (const float*)d_in[1];
    const float* vh   = (const float*)d_in[2];
    const float* cmap = (const float*)d_in[3];
    const float* Wq   = (const float*)d_in[4];
    const float* bq   = (const float*)d_in[5];
    const float* Wk   = (const float*)d_in[6];
    const float* bk   = (const float*)d_in[7];
    const float* Wv   = (const float*)d_in[8];
    const float* bv   = (const float*)d_in[9];
    const float* Wo   = (const float*)d_in[10];
    const float* bo   = (const float*)d_in[11];
    float* out = (float*)d_out;

    uint32_t *pq, *pk, *pv, *px, *pw, *pfq, *pfk, *pfv;
    int* pidx;
    cudaGetSymbolAddress((void**)&pq,   g_q);
    cudaGetSymbolAddress((void**)&pk,   g_k);
    cudaGetSymbolAddress((void**)&pv,   g_v);
    cudaGetSymbolAddress((void**)&px,   g_x);
    cudaGetSymbolAddress((void**)&pw,   g_w);
    cudaGetSymbolAddress((void**)&pfq,  g_fq);
    cudaGetSymbolAddress((void**)&pfk,  g_fk);
    cudaGetSymbolAddress((void**)&pfv,  g_fv);
    cudaGetSymbolAddress((void**)&pidx, g_idx);

    cudaFuncSetAttribute(gemm_proj, cudaFuncAttributeMaxDynamicSharedMemorySize, P_GSM);
    cudaFuncSetAttribute(gemm_out, cudaFuncAttributeMaxDynamicSharedMemorySize, O_GSM);
    cudaFuncSetAttribute(attn_kernel, cudaFuncAttributeMaxDynamicSharedMemorySize, A_SM);

    prep_kernel<<<960, 256>>>(cmap, pidx, Wq, Wk, Wv, Wo, pw,
                              qh, kh, vh, pfq, pfk, pfv);

    dim3 gp(NPIX / 128, CDIM / 128, 6);
    gemm_proj<<<gp, 256, P_GSM>>>(pfq, pfk, pfv, pw, bq, bk, bv, pq, pk, pv);

    attn_kernel<<<dim3(NLOW, BATCH, 2), 128, A_SM>>>(pq, pk, pv, pidx, px);

    dim3 go(CDIM / 64, NPIX / 128, BATCH);
    gemm_out<<<go, 256, O_GSM>>>(px, pw, bo, out);
}

// round 17
// speedup vs baseline: 1.2312x; 1.0007x over previous
#include <cuda_runtime.h>
#include <math.h>
#include <stdint.h>

#define NPIX 4096
#define CDIM 256
#define NLOW 256
#define KLEN 32
#define BATCH 2
#define CW 128              // words (half2) per channel row

// ---------------- scratch (no allocations allowed) ----------------
__device__ float    g_q[BATCH * NPIX * CDIM];   // proj outputs, half2 words
__device__ float    g_k[BATCH * NPIX * CDIM];
__device__ float    g_v[BATCH * NPIX * CDIM];
__device__ float    g_x[BATCH * NPIX * CDIM];
__device__ uint32_t g_fq[BATCH * NPIX * CW];    // pre-converted features, half2 [b][pix][kp]
__device__ uint32_t g_fk[BATCH * NPIX * CW];
__device__ uint32_t g_fv[BATCH * NPIX * CW];
__device__ uint32_t g_w[4 * CDIM * CDIM / 2];   // W^T as half2: [which][cout][k/2]
__device__ int      g_idx[BATCH * NLOW * KLEN];

// ---------------- helpers ----------------
__device__ __forceinline__ uint32_t pk2(float lo, float hi) {
    uint32_t r;
    asm("cvt.rn.f16x2.f32 %0, %1, %2;" : "=r"(r) : "f"(hi), "f"(lo));
    return r;
}
__device__ __forceinline__ uint32_t prmt(uint32_t a, uint32_t b, uint32_t sel) {
    uint32_t r;
    asm("prmt.b32 %0, %1, %2, %3;" : "=r"(r) : "r"(a), "r"(b), "r"(sel));
    return r;
}
__device__ __forceinline__ void mma_f16(float* c, const uint32_t* a, const uint32_t* b) {
    asm volatile(
        "mma.sync.aligned.m16n8k16.row.col.f32.f16.f16.f32 "
        "{%0,%1,%2,%3},{%4,%5,%6,%7},{%8,%9},{%0,%1,%2,%3};"
        : "+f"(c[0]), "+f"(c[1]), "+f"(c[2]), "+f"(c[3])
        : "r"(a[0]), "r"(a[1]), "r"(a[2]), "r"(a[3]), "r"(b[0]), "r"(b[1]));
}
__device__ __forceinline__ void cp16(const void* dst, const void* src) {
    uint32_t d = (uint32_t)__cvta_generic_to_shared(dst);
    asm volatile("cp.async.cg.shared.global [%0], [%1], 16;" :: "r"(d), "l"(src));
}
#define CP_COMMIT() asm volatile("cp.async.commit_group;" ::: "memory")
#define CP_WAIT0()  asm volatile("cp.async.wait_group 0;" ::: "memory")
#define CP_WAIT1()  asm volatile("cp.async.wait_group 1;" ::: "memory")
// progressive wait: data for chunk c ready when <= (3-c) groups pending
#define CP_WAIT_PROG(c) do { \
    if      ((c) == 0) asm volatile("cp.async.wait_group 3;" ::: "memory"); \
    else if ((c) == 1) asm volatile("cp.async.wait_group 2;" ::: "memory"); \
    else if ((c) == 2) asm volatile("cp.async.wait_group 1;" ::: "memory"); \
    else               asm volatile("cp.async.wait_group 0;" ::: "memory"); \
} while (0)

// ---------------- prep: topk (0..63) + weight transpose (64..191) + feature convert (192..959) ----------------
__global__ __launch_bounds__(256) void prep_kernel(const float* __restrict__ cmap,
                                                   int* __restrict__ idx,
                                                   const float* __restrict__ Wq,
                                                   const float* __restrict__ Wk,
                                                   const float* __restrict__ Wv,
                                                   const float* __restrict__ Wo,
                                                   uint32_t* __restrict__ wt,
                                                   const float* __restrict__ qh,
                                                   const float* __restrict__ kh,
                                                   const float* __restrict__ vh,
                                                   uint32_t* __restrict__ fq,
                                                   uint32_t* __restrict__ fk,
                                                   uint32_t* __restrict__ fv) {
    __shared__ float sm[64 * 132];
    int t = threadIdx.x;
    if (blockIdx.x < 64) {
        int lane = t & 31;
        int row  = blockIdx.x * 8 + (t >> 5);
        const float* r = cmap + (size_t)row * NLOW;
        float m1 = -1e30f, m2 = -1e30f;
        int i1 = 0, i2 = 0;
        #pragma unroll
        for (int l = 0; l < 8; l++) {
            int j = l * 32 + lane;
            float v = r[j];
            if (v > m1)      { m2 = m1; i2 = i1; m1 = v; i1 = j; }
            else if (v > m2) { m2 = v;  i2 = j; }
        }
        #pragma unroll
        for (int off = 16; off > 0; off >>= 1) {
            float om1 = __shfl_xor_sync(0xffffffffu, m1, off);
            float om2 = __shfl_xor_sync(0xffffffffu, m2, off);
            int   oi1 = __shfl_xor_sync(0xffffffffu, i1, off);
            int   oi2 = __shfl_xor_sync(0xffffffffu, i2, off);
            if (om1 > m1) {
                if (m1 > om2) { m2 = m1; i2 = i1; } else { m2 = om2; i2 = oi2; }
                m1 = om1; i1 = oi1;
            } else if (om1 > m2) { m2 = om1; i2 = oi1; }
        }
        int tk  = (lane < 16) ? i1 : i2;
        int pos = lane & 15;
        int r0  = (tk >> 4) << 2;
        int c0  = (tk & 15) << 2;
        idx[(size_t)row * KLEN + lane] = (r0 + (pos >> 2)) * 64 + c0 + (pos & 3);
    } else if (blockIdx.x < 192) {
        int bi = blockIdx.x - 64;
        int which = bi >> 5;
        int tile  = bi & 31;
        int c0 = (tile >> 2) * 32;
        int k0 = (tile & 3) * 64;
        const float* W = (which == 0) ? Wq : (which == 1) ? Wk : (which == 2) ? Wv : Wo;
        #pragma unroll
        for (int p = 0; p < 8; p++) {
            int i = p * 256 + t;
            int row = i >> 5, c = i & 31;
            sm[row * 33 + c] = W[(size_t)(k0 + row) * CDIM + c0 + c];
        }
        __syncthreads();
        #pragma unroll
        for (int p = 0; p < 4; p++) {
            int i = p * 256 + t;
            int cc = i >> 5, kp = i & 31;
            wt[(size_t)which * 32768 + (size_t)(c0 + cc) * CW + (k0 >> 1) + kp] =
                pk2(sm[(2 * kp) * 33 + cc], sm[(2 * kp + 1) * 33 + cc]);
        }
    } else {
        int bi = blockIdx.x - 192;             // 0..767
        int which = bi >> 7;
        int tile  = bi & 127;
        int k0 = (tile >> 5) * 64;
        int p0 = (tile & 31) * 128;
        int mat = which >> 1, b = which & 1;
        const float* src = ((mat == 0) ? qh : (mat == 1) ? kh : vh) + (size_t)b * CDIM * NPIX;
        uint32_t* dst = ((mat == 0) ? fq : (mat == 1) ? fk : fv) + (size_t)b * NPIX * CW;
        #pragma unroll
        for (int p = 0; p < 8; p++) {
            int i = p * 256 + t;
            int row = i >> 5, c4 = (i & 31) * 4;
            *(float4*)&sm[row * 132 + c4] =
                *(const float4*)&src[(size_t)(k0 + row) * NPIX + p0 + c4];
        }
        __syncthreads();
        #pragma unroll
        for (int p = 0; p < 4; p++) {
            int i = p * 256 + t;
            int pix = i >> 3, kq = (i & 7) * 4;
            uint4 r;
            r.x = pk2(sm[(2 * kq + 0) * 132 + pix], sm[(2 * kq + 1) * 132 + pix]);
            r.y = pk2(sm[(2 * kq + 2) * 132 + pix], sm[(2 * kq + 3) * 132 + pix]);
            r.z = pk2(sm[(2 * kq + 4) * 132 + pix], sm[(2 * kq + 5) * 132 + pix]);
            r.w = pk2(sm[(2 * kq + 6) * 132 + pix], sm[(2 * kq + 7) * 132 + pix]);
            *(uint4*)&dst[(size_t)(p0 + pix) * CW + (k0 >> 1) + kq] = r;
        }
    }
}

// ---------------- fp16 QKV projection: CTA 128pix x 128cout, full-K prefetch ----------------
// 8 warps = 4(m)x2(n); warp tile 32m x 64n; 4 chunks of 64 k (32 kp); pitch 36.
// All 4 chunk loads issued at entry (4 commit groups); progressive waits.
#define P_AW 36
#define P_STW (256 * P_AW)          // 9216 words per stage
#define P_GSM (4 * P_STW * 4)       // 147456 B

__global__ __launch_bounds__(256) void gemm_proj(
    const uint32_t* __restrict__ fq, const uint32_t* __restrict__ fk, const uint32_t* __restrict__ fv,
    const uint32_t* __restrict__ wt,
    const float* __restrict__ bq, const float* __restrict__ bk, const float* __restrict__ bv,
    uint32_t* __restrict__ oq, uint32_t* __restrict__ ok2, uint32_t* __restrict__ ov) {
    extern __shared__ uint32_t sw[];
    int m0 = blockIdx.x * 128;                 // pixels
    int c0 = blockIdx.y * 128;                 // couts
    int t = threadIdx.x;
    int lane = t & 31, w = t >> 5;
    int wm = w & 3, wc = w >> 2;
    int g = lane >> 2, tq = lane & 3;

    int which = blockIdx.z >> 1, b = blockIdx.z & 1;
    const uint32_t* PF = ((which == 0) ? fq : (which == 1) ? fk : fv) + (size_t)b * NPIX * CW;
    const uint32_t* PB = wt + (size_t)which * 32768;
    const float* bias = (which == 0) ? bq : (which == 1) ? bk : bv;
    uint32_t* Out = (which == 0) ? oq : (which == 1) ? ok2 : ov;
    uint32_t* outp = Out + (size_t)b * NPIX * CW;

    float acc[2][8][4];
    #pragma unroll
    for (int ms = 0; ms < 2; ms++)
        #pragma unroll
        for (int cs = 0; cs < 8; cs++)
            #pragma unroll
            for (int r = 0; r < 4; r++) acc[ms][cs][r] = 0.f;

    // issue ALL chunk loads upfront (4 commit groups)
    #pragma unroll
    for (int s = 0; s < 4; s++) {
        uint32_t* A_ = sw + s * P_STW;
        uint32_t* B_ = A_ + 128 * P_AW;
        int kph = s * 32;                      // kp offset of chunk
        #pragma unroll
        for (int p = 0; p < 4; p++) {
            int idx = p * 256 + t;
            int n = idx >> 3, q = idx & 7;
            cp16(&A_[n * P_AW + q * 4], &PF[(size_t)(m0 + n) * CW + kph + q * 4]);
        }
        #pragma unroll
        for (int p = 0; p < 4; p++) {
            int idx = p * 256 + t;
            int n = idx >> 3, q = idx & 7;
            cp16(&B_[n * P_AW + q * 4], &PB[(size_t)(c0 + n) * CW + kph + q * 4]);
        }
        CP_COMMIT();
    }

    #pragma unroll
    for (int c = 0; c < 4; c++) {
        CP_WAIT_PROG(c);
        __syncthreads();
        uint32_t* A_ = sw + c * P_STW;
        uint32_t* B_ = A_ + 128 * P_AW;
        #pragma unroll
        for (int kc = 0; kc < 4; kc++) {
            uint32_t a[2][4], bb[8][2];
            #pragma unroll
            for (int ms = 0; ms < 2; ms++) {
                int base = (wm * 32 + ms * 16 + g) * P_AW + kc * 8 + tq;
                a[ms][0] = A_[base];
                a[ms][1] = A_[base + 8 * P_AW];
                a[ms][2] = A_[base + 4];
                a[ms][3] = A_[base + 8 * P_AW + 4];
            }
            #pragma unroll
            for (int cs = 0; cs < 8; cs++) {
                int bbase = (wc * 64 + cs * 8 + g) * P_AW + kc * 8 + tq;
                bb[cs][0] = B_[bbase];
                bb[cs][1] = B_[bbase + 4];
            }
            #pragma unroll
            for (int ms = 0; ms < 2; ms++)
                #pragma unroll
                for (int cs = 0; cs < 8; cs++)
                    mma_f16(acc[ms][cs], a[ms], bb[cs]);
        }
    }

    #pragma unroll
    for (int ms = 0; ms < 2; ms++) {
        int r0 = m0 + wm * 32 + ms * 16 + g;
        int r1 = r0 + 8;
        #pragma unroll
        for (int cs = 0; cs < 8; cs++) {
            int c = c0 + wc * 64 + cs * 8 + 2 * tq;
            float2 b2 = *(const float2*)&bias[c];
            outp[(size_t)r0 * CW + (c >> 1)] = pk2(acc[ms][cs][0] + b2.x, acc[ms][cs][1] + b2.y);
            outp[(size_t)r1 * CW + (c >> 1)] = pk2(acc[ms][cs][2] + b2.x, acc[ms][cs][3] + b2.y);
        }
    }
}

// ---------------- fp16 output GEMM: CTA 64cout x 128pix, full-K prefetch ----------------
#define O_STW ((64 + 128) * P_AW)        // 6912 words per stage
#define O_GSM (4 * O_STW * 4)            // 110592 B

__global__ __launch_bounds__(256) void gemm_out(
    const uint32_t* __restrict__ xw, const uint32_t* __restrict__ wt,
    const float* __restrict__ bo, float* __restrict__ out) {
    extern __shared__ uint32_t sw[];
    int m0 = blockIdx.x * 64;                  // couts
    int n0 = blockIdx.y * 128;                 // pixels
    int t = threadIdx.x;
    int lane = t & 31, w = t >> 5;
    int wm = w & 1, wc = w >> 1;
    int g = lane >> 2, tq = lane & 3;

    int b = blockIdx.z;
    const uint32_t* PA = wt + 3 * 32768;                 // Wo^T [cout][kp]
    const uint32_t* PB = xw + (size_t)b * NPIX * CW;     // x [pix][kp]
    float* outp = out + (size_t)b * CDIM * NPIX;

    float acc[2][4][4];
    #pragma unroll
    for (int ms = 0; ms < 2; ms++)
        #pragma unroll
        for (int cs = 0; cs < 4; cs++)
            #pragma unroll
            for (int r = 0; r < 4; r++) acc[ms][cs][r] = 0.f;

    // issue ALL chunk loads upfront (4 commit groups)
    #pragma unroll
    for (int s = 0; s < 4; s++) {
        uint32_t* A_ = sw + s * O_STW;
        uint32_t* B_ = A_ + 64 * P_AW;
        int kph = s * 32;
        #pragma unroll
        for (int p = 0; p < 2; p++) {
            int idx = p * 256 + t;
            int n = idx >> 3, q = idx & 7;
            cp16(&A_[n * P_AW + q * 4], &PA[(size_t)(m0 + n) * CW + kph + q * 4]);
        }
        #pragma unroll
        for (int p = 0; p < 4; p++) {
            int idx = p * 256 + t;
            int n = idx >> 3, q = idx & 7;
            cp16(&B_[n * P_AW + q * 4], &PB[(size_t)(n0 + n) * CW + kph + q * 4]);
        }
        CP_COMMIT();
    }

    #pragma unroll
    for (int c = 0; c < 4; c++) {
        CP_WAIT_PROG(c);
        __syncthreads();
        uint32_t* A_ = sw + c * O_STW;
        uint32_t* B_ = A_ + 64 * P_AW;
        #pragma unroll
        for (int kc = 0; kc < 4; kc++) {
            uint32_t a[2][4], bb[4][2];
            #pragma unroll
            for (int ms = 0; ms < 2; ms++) {
                int base = (wm * 32 + ms * 16 + g) * P_AW + kc * 8 + tq;
                a[ms][0] = A_[base];
                a[ms][1] = A_[base + 8 * P_AW];
                a[ms][2] = A_[base + 4];
                a[ms][3] = A_[base + 8 * P_AW + 4];
            }
            #pragma unroll
            for (int cs = 0; cs < 4; cs++) {
                int bbase = (wc * 32 + cs * 8 + g) * P_AW + kc * 8 + tq;
                bb[cs][0] = B_[bbase];
                bb[cs][1] = B_[bbase + 4];
            }
            #pragma unroll
            for (int ms = 0; ms < 2; ms++)
                #pragma unroll
                for (int cs = 0; cs < 4; cs++)
                    mma_f16(acc[ms][cs], a[ms], bb[cs]);
        }
    }

    #pragma unroll
    for (int ms = 0; ms < 2; ms++) {
        int r0 = m0 + wm * 32 + ms * 16 + g;
        int r1 = r0 + 8;
        float b0v = bo[r0], b1v = bo[r1];
        #pragma unroll
        for (int cs = 0; cs < 4; cs++) {
            int c = n0 + wc * 32 + cs * 8 + 2 * tq;
            float2 v0 = {acc[ms][cs][0] + b0v, acc[ms][cs][1] + b0v};
            float2 v1 = {acc[ms][cs][2] + b1v, acc[ms][cs][3] + b1v};
            *(float2*)&outp[(size_t)r0 * NPIX + c] = v0;
            *(float2*)&outp[(size_t)r1 * NPIX + c] = v1;
        }
    }
}

// ---------------- fp16 tensor-core sparse attention (R11 exact) ----------------
#define AKW 68
#define A_KS 0
#define A_VR (32 * AKW)
#define A_QS (A_VR + 32 * AKW)
#define A_VT (A_QS + 16 * AKW)
#define A_PS (A_VT + 128 * 20)
#define A_SM ((A_PS + 4 * 320) * 4)

__global__ __launch_bounds__(128) void attn_kernel(const uint32_t* __restrict__ qw,
                                                   const uint32_t* __restrict__ kw,
                                                   const uint32_t* __restrict__ vw,
                                                   const int* __restrict__ idx,
                                                   uint32_t* __restrict__ xw) {
    int qlow = blockIdx.x;
    int b    = blockIdx.y;
    int hh   = blockIdx.z;
    extern __shared__ uint32_t smu[];
    uint32_t* Ks = smu + A_KS;
    uint32_t* Vr = smu + A_VR;
    uint32_t* Qs = smu + A_QS;
    uint32_t* Vt = smu + A_VT;
    uint32_t* Ps = smu + A_PS;
    __shared__ int sidx[KLEN];
    int t = threadIdx.x;
    int lane = t & 31, w = t >> 5;
    if (t < KLEN) sidx[t] = idx[((size_t)b * NLOW + qlow) * KLEN + t];
    __syncthreads();

    size_t bN = (size_t)b * NPIX;
    int hho = hh * 64;

    #pragma unroll
    for (int p = 0; p < 2; p++) {
        int li = p * 128 + t;
        int r = li >> 4, q4 = li & 15;
        cp16(&Qs[r * AKW + q4 * 4], &qw[(bN + qlow * 16 + r) * CW + hho + q4 * 4]);
    }
    #pragma unroll
    for (int p = 0; p < 4; p++) {
        int li = p * 128 + t;
        int r = li >> 4, q4 = li & 15;
        cp16(&Ks[r * AKW + q4 * 4], &kw[(bN + sidx[r]) * CW + hho + q4 * 4]);
    }
    CP_COMMIT();
    #pragma unroll
    for (int p = 0; p < 4; p++) {
        int li = p * 128 + t;
        int r = li >> 4, q4 = li & 15;
        cp16(&Vr[r * AKW + q4 * 4], &vw[(bN + sidx[r]) * CW + hho + q4 * 4]);
    }
    CP_COMMIT();

    int g = lane >> 2, tq = lane & 3;
    int hw = w * 16;

    CP_WAIT1();
    __syncthreads();

    uint32_t aq[2][4];
    #pragma unroll
    for (int kc = 0; kc < 2; kc++) {
        int base = g * AKW + hw + kc * 8 + tq;
        aq[kc][0] = Qs[base];
        aq[kc][1] = Qs[base + 8 * AKW];
        aq[kc][2] = Qs[base + 4];
        aq[kc][3] = Qs[base + 8 * AKW + 4];
    }

    float sc[4][4];
    #pragma unroll
    for (int nt = 0; nt < 4; nt++)
        #pragma unroll
        for (int r = 0; r < 4; r++) sc[nt][r] = 0.f;
    #pragma unroll
    for (int nt = 0; nt < 4; nt++) {
        #pragma unroll
        for (int kc = 0; kc < 2; kc++) {
            uint32_t bK[2];
            int bbase = (nt * 8 + g) * AKW + hw + kc * 8 + tq;
            bK[0] = Ks[bbase];
            bK[1] = Ks[bbase + 4];
            mma_f16(sc[nt], aq[kc], bK);
        }
    }

    const float scale = 0.17677669529663687f;
    float mx0 = -1e30f, mx1 = -1e30f;
    #pragma unroll
    for (int nt = 0; nt < 4; nt++) {
        #pragma unroll
        for (int r = 0; r < 4; r++) sc[nt][r] *= scale;
        mx0 = fmaxf(mx0, fmaxf(sc[nt][0], sc[nt][1]));
        mx1 = fmaxf(mx1, fmaxf(sc[nt][2], sc[nt][3]));
    }
    #pragma unroll
    for (int o = 1; o <= 2; o <<= 1) {
        mx0 = fmaxf(mx0, __shfl_xor_sync(0xffffffffu, mx0, o));
        mx1 = fmaxf(mx1, __shfl_xor_sync(0xffffffffu, mx1, o));
    }
    float sum0 = 0.f, sum1 = 0.f;
    #pragma unroll
    for (int nt = 0; nt < 4; nt++) {
        sc[nt][0] = __expf(sc[nt][0] - mx0);
        sc[nt][1] = __expf(sc[nt][1] - mx0);
        sc[nt][2] = __expf(sc[nt][2] - mx1);
        sc[nt][3] = __expf(sc[nt][3] - mx1);
        sum0 += sc[nt][0] + sc[nt][1];
        sum1 += sc[nt][2] + sc[nt][3];
    }
    #pragma unroll
    for (int o = 1; o <= 2; o <<= 1) {
        sum0 += __shfl_xor_sync(0xffffffffu, sum0, o);
        sum1 += __shfl_xor_sync(0xffffffffu, sum1, o);
    }

    CP_WAIT0();
    __syncthreads();

    #pragma unroll
    for (int p = 0; p < 16; p++) {
        int li = p * 128 + t;
        int d = li & 127, kp = li >> 7;
        uint32_t w0 = Vr[(2 * kp) * AKW + (d >> 1)];
        uint32_t w1 = Vr[(2 * kp + 1) * AKW + (d >> 1)];
        uint32_t sel = (d & 1) ? 0x7632u : 0x5410u;
        Vt[d * 20 + kp] = prmt(w0, w1, sel);
    }

    uint32_t* Pw = Ps + w * 320;
    #pragma unroll
    for (int nt = 0; nt < 4; nt++) {
        Pw[g * 20 + nt * 4 + tq]       = pk2(sc[nt][0], sc[nt][1]);
        Pw[(g + 8) * 20 + nt * 4 + tq] = pk2(sc[nt][2], sc[nt][3]);
    }
    __syncthreads();

    float oc[4][4];
    #pragma unroll
    for (int nt = 0; nt < 4; nt++)
        #pragma unroll
        for (int r = 0; r < 4; r++) oc[nt][r] = 0.f;
    int hd = w * 32;
    #pragma unroll
    for (int kc = 0; kc < 2; kc++) {
        uint32_t ap[4];
        ap[0] = Pw[g * 20 + kc * 8 + tq];
        ap[1] = Pw[(g + 8) * 20 + kc * 8 + tq];
        ap[2] = Pw[g * 20 + kc * 8 + tq + 4];
        ap[3] = Pw[(g + 8) * 20 + kc * 8 + tq + 4];
        #pragma unroll
        for (int nt = 0; nt < 4; nt++) {
            uint32_t bV[2];
            int bbase = (hd + nt * 8 + g) * 20 + kc * 8 + tq;
            bV[0] = Vt[bbase];
            bV[1] = Vt[bbase + 4];
            mma_f16(oc[nt], ap, bV);
        }
    }

    float inv0 = 1.f / sum0, inv1 = 1.f / sum1;
    uint32_t* x0 = xw + (bN + qlow * 16 + g) * CW + hho + hw;
    uint32_t* x1 = x0 + 8 * CW;
    #pragma unroll
    for (int nt = 0; nt < 4; nt++) {
        x0[nt * 4 + tq] = pk2(oc[nt][0] * inv0, oc[nt][1] * inv0);
        x1[nt * 4 + tq] = pk2(oc[nt][2] * inv1, oc[nt][3] * inv1);
    }
}

// ---------------- launch ----------------
extern "C" void kernel_launch(void* const* d_in, const int* in_sizes, int n_in,
                              void* d_out, int out_size) {
    const float* qh   = (const float*)d_in[0];
    const float* kh   = (const float*)d_in[1];
    const float* vh   = (const float*)d_in[2];
    const float* cmap = (const float*)d_in[3];
    const float* Wq   = (const float*)d_in[4];
    const float* bq   = (const float*)d_in[5];
    const float* Wk   = (const float*)d_in[6];
    const float* bk   = (const float*)d_in[7];
    const float* Wv   = (const float*)d_in[8];
    const float* bv   = (const float*)d_in[9];
    const float* Wo   = (const float*)d_in[10];
    const float* bo   = (const float*)d_in[11];
    float* out = (float*)d_out;

    uint32_t *pq, *pk, *pv, *px, *pw, *pfq, *pfk, *pfv;
    int* pidx;
    cudaGetSymbolAddress((void**)&pq,   g_q);
    cudaGetSymbolAddress((void**)&pk,   g_k);
    cudaGetSymbolAddress((void**)&pv,   g_v);
    cudaGetSymbolAddress((void**)&px,   g_x);
    cudaGetSymbolAddress((void**)&pw,   g_w);
    cudaGetSymbolAddress((void**)&pfq,  g_fq);
    cudaGetSymbolAddress((void**)&pfk,  g_fk);
    cudaGetSymbolAddress((void**)&pfv,  g_fv);
    cudaGetSymbolAddress((void**)&pidx, g_idx);

    cudaFuncSetAttribute(gemm_proj, cudaFuncAttributeMaxDynamicSharedMemorySize, P_GSM);
    cudaFuncSetAttribute(gemm_out, cudaFuncAttributeMaxDynamicSharedMemorySize, O_GSM);
    cudaFuncSetAttribute(attn_kernel, cudaFuncAttributeMaxDynamicSharedMemorySize, A_SM);

    prep_kernel<<<960, 256>>>(cmap, pidx, Wq, Wk, Wv, Wo, pw,
                              qh, kh, vh, pfq, pfk, pfv);

    dim3 gp(NPIX / 128, CDIM / 128, 6);
    gemm_proj<<<gp, 256, P_GSM>>>(pfq, pfk, pfv, pw, bq, bk, bv, pq, pk, pv);

    attn_kernel<<<dim3(NLOW, BATCH, 2), 128, A_SM>>>(pq, pk, pv, pidx, px);

    dim3 go(CDIM / 64, NPIX / 128, BATCH);
    gemm_out<<<go, 256, O_GSM>>>(px, pw, bo, out);
}